// round 15
// baseline (speedup 1.0000x reference)
#include <cuda_runtime.h>
#include <cstdint>
#include <math.h>

#define BB 8
#define PP 24
#define CC 16
#define DD 256
#define NN 1024
#define KF 13
#define RTOT (BB*NN)      // 8192

// ---------------- scratch (device globals; no allocations) ----------------
__device__ __align__(128) float g_xc[(size_t)KF*RTOT*32];   // per-k [re(16)|im(16)]
__device__ __align__(128) float g_xatt[RTOT*CC];
__device__ __align__(128) float g_hf1[RTOT*DD];
__device__ __align__(128) float g_zpart[RTOT*DD];
__device__ __align__(128) float g_time_emb[BB*PP*DD];
__device__ __align__(128) float g_periodic[PP*128];
__device__ float g_base_att[PP];
__device__ float g_att[BB*PP];
__device__ float g_dd[BB*4*PP];
__device__ float g_tw[2*KF*PP];
__device__ float g_zero[DD];
__device__ float g_bconst[DD];
__device__ float g_bcp[KF*DD];
__device__ __align__(128) float g_tere[KF*BB*DD];
__device__ __align__(128) float g_teim[KF*BB*DD];
__device__ __align__(128) float g_teatt[BB*DD];
__device__ __align__(128) float g_ckb[KF*BB*DD];
// derived weights
__device__ __align__(128) float g_wp1T[KF*DD*32];      // [(k,o),32] = W@W1 fold, K-major
__device__ __align__(128) float g_uvp[KF*4*DD*32];     // k_uv partials
__device__ __align__(128) float g_wc1T[KF*DD*DD];
__device__ __align__(128) float g_weffT[KF*DD*DD];
__device__ __align__(128) float g_wc2T[DD*DD];
// fragment-permuted, tf32-rounded copies for k_ff
__device__ __align__(128) float g_weffP[(size_t)KF*2*8*4096];
__device__ __align__(128) float g_wp1P[KF*2*4096];

__device__ __forceinline__ float gelu_f(float v) {
    return 0.5f*v*(1.f + erff(v*0.70710678118654752f));
}
__device__ __forceinline__ float softplus_f(float v) {
    return fmaxf(v, 0.f) + log1pf(expf(-fabsf(v)));
}
__device__ void isort(float* a, int n) {
    for (int i = 1; i < n; i++) {
        float v = a[i]; int j = i-1;
        while (j >= 0 && a[j] > v) { a[j+1] = a[j]; j--; }
        a[j+1] = v;
    }
}
__device__ __forceinline__ float tf32r(float x) {
    uint32_t r;
    asm("cvt.rna.tf32.f32 %0, %1;" : "=r"(r) : "f"(x));
    return __uint_as_float(r);
}
__device__ __forceinline__ uint32_t smem_u32(const void* p) {
    uint32_t a;
    asm("{ .reg .u64 t; cvta.to.shared.u64 t, %1; cvt.u32.u64 %0, t; }" : "=r"(a) : "l"(p));
    return a;
}
#define CP_ASYNC16(smaddr, gptr) \
    asm volatile("cp.async.ca.shared.global [%0], [%1], 16;" :: "r"(smaddr), "l"(gptr))
#define CP_COMMIT() asm volatile("cp.async.commit_group;" ::: "memory")
#define CP_WAIT0()  asm volatile("cp.async.wait_group 0;" ::: "memory")

// ---------------- warp mma m16n8k8 tf32 ------------------------------------
__device__ __forceinline__ void mma_tf32(float* d, const float4& a, const float2& b) {
    asm volatile("mma.sync.aligned.m16n8k8.row.col.f32.tf32.tf32.f32 "
        "{%0,%1,%2,%3}, {%4,%5,%6,%7}, {%8,%9}, {%0,%1,%2,%3};"
        : "+f"(d[0]), "+f"(d[1]), "+f"(d[2]), "+f"(d[3])
        : "r"(__float_as_uint(a.x)), "r"(__float_as_uint(a.y)),
          "r"(__float_as_uint(a.z)), "r"(__float_as_uint(a.w)),
          "r"(__float_as_uint(b.x)), "r"(__float_as_uint(b.y)));
}

// GEMM building blocks (CTA tile 128x128, 8 warps, K-chunk 32) -- for k_mma
__device__ __forceinline__ void gload(const float* A, const float* Wt, int bm, int bn,
                                      int K, int koff, int tid, float4* ra, float4* rb)
{
    #pragma unroll
    for (int q = 0; q < 4; q++) {
        int f = tid + q*256;
        int row = f >> 3, seg = f & 7;
        ra[q] = *(const float4*)(A  + (size_t)(bm + row)*K + koff + seg*4);
        rb[q] = *(const float4*)(Wt + (size_t)(bn + row)*K + koff + seg*4);
    }
}
__device__ __forceinline__ void gscatter(const float4* ra, const float4* rb,
                                         float* sa, float* sb, int tid)
{
    #pragma unroll
    for (int q = 0; q < 4; q++) {
        int f = tid + q*256;
        int row = f >> 3, seg = f & 7;
        int ks = seg >> 1, posK = seg & 1;
        int mt = row >> 4, posM = (row >> 3) & 1, gga = row & 7;
        int abase = ((mt*4 + ks)*32 + gga*4)*4 + posK*2 + posM;
        float av[4] = {ra[q].x, ra[q].y, ra[q].z, ra[q].w};
        #pragma unroll
        for (int e = 0; e < 4; e++) sa[abase + e*4] = tf32r(av[e]);
        int nt = row >> 3, ggb = row & 7;
        int bbase = ((nt*4 + ks)*32 + ggb*4)*2 + posK;
        float bv[4] = {rb[q].x, rb[q].y, rb[q].z, rb[q].w};
        #pragma unroll
        for (int e = 0; e < 4; e++) sb[bbase + e*2] = tf32r(bv[e]);
    }
}
__device__ __forceinline__ void gmma(const float* sa, const float* sb,
                                     int wid, int lane, float acc[2][8][4])
{
    #pragma unroll
    for (int ks = 0; ks < 4; ks++) {
        float4 af[2];
        #pragma unroll
        for (int i = 0; i < 2; i++) {
            int mt = (wid & 3)*2 + i;
            af[i] = *(const float4*)&sa[((mt*4 + ks)*32 + lane)*4];
        }
        float2 bf[8];
        #pragma unroll
        for (int j = 0; j < 8; j++) {
            int nt = (wid >> 2)*8 + j;
            bf[j] = *(const float2*)&sb[((nt*4 + ks)*32 + lane)*2];
        }
        #pragma unroll
        for (int i = 0; i < 2; i++)
            #pragma unroll
            for (int j = 0; j < 8; j++)
                mma_tf32(acc[i][j], af[i], bf[j]);
    }
}
// M=64 variant: A chunk 64x32 (layout mt=row>>4 in 0..3), warp tile 16x64
__device__ __forceinline__ void gmma64(const float* sa, const float* sb,
                                       int wid, int lane, float acc[8][4])
{
    #pragma unroll
    for (int ks = 0; ks < 4; ks++) {
        int mt = wid & 3;
        float4 af = *(const float4*)&sa[((mt*4 + ks)*32 + lane)*4];
        float2 bf[8];
        #pragma unroll
        for (int j = 0; j < 8; j++) {
            int nt = (wid >> 2)*8 + j;
            bf[j] = *(const float2*)&sb[((nt*4 + ks)*32 + lane)*2];
        }
        #pragma unroll
        for (int j = 0; j < 8; j++)
            mma_tf32(acc[j], af, bf[j]);
    }
}

// ---------------- generic GEMM: C = act(A @ Wt^T + bias) -------------------
template<int ACT, int FIN>
__global__ void __launch_bounds__(256) k_mma(
    const float* __restrict__ A, const float* __restrict__ Wt,
    const float* __restrict__ bias, float* __restrict__ C,
    int K, int ldc, long sA, long sW, long sB, long sC, int bstride)
{
    extern __shared__ float smem[];
    float* sa0 = smem;         float* sa1 = smem + 4096;
    float* sb0 = smem + 8192;  float* sb1 = smem + 12288;
    int z = blockIdx.z;
    int bm = blockIdx.y*128, bn = blockIdx.x*128;
    A    += (size_t)z*sA;
    Wt   += (size_t)z*sW;
    bias += (size_t)z*sB + (size_t)(bm >> 10)*bstride;
    C    += (size_t)z*sC;
    int tid = threadIdx.x, wid = tid >> 5, lane = tid & 31;
    int g = lane >> 2, tig = lane & 3;
    int wm = (wid & 3)*32, wn = (wid >> 2)*64;

    float acc[2][8][4];
    #pragma unroll
    for (int i = 0; i < 2; i++)
        #pragma unroll
        for (int j = 0; j < 8; j++)
            #pragma unroll
            for (int q = 0; q < 4; q++) acc[i][j][q] = 0.f;

    int nch = K >> 5;
    float4 ra[4], rb[4];
    gload(A, Wt, bm, bn, K, 0, tid, ra, rb);
    gscatter(ra, rb, sa0, sb0, tid);
    __syncthreads();
    for (int c = 0; c < nch; c++) {
        int buf = c & 1;
        if (c + 1 < nch) gload(A, Wt, bm, bn, K, (c+1)*32, tid, ra, rb);
        gmma(buf ? sa1 : sa0, buf ? sb1 : sb0, wid, lane, acc);
        if (c + 1 < nch) gscatter(ra, rb, buf ? sa0 : sa1, buf ? sb0 : sb1, tid);
        __syncthreads();
    }

    #pragma unroll
    for (int i = 0; i < 2; i++) {
        int r0 = bm + wm + i*16 + g;
        #pragma unroll
        for (int j = 0; j < 8; j++) {
            int col = bn + wn + j*8 + tig*2;
            float b0 = bias[col], b1 = bias[col+1];
            float v0 = acc[i][j][0] + b0, v1 = acc[i][j][1] + b1;
            float v2 = acc[i][j][2] + b0, v3 = acc[i][j][3] + b1;
            if (ACT) { v0 = gelu_f(v0); v1 = gelu_f(v1); v2 = gelu_f(v2); v3 = gelu_f(v3); }
            if (FIN) {
                v0 = g_zpart[(size_t)r0*ldc + col]       + 0.3f*v0;
                v1 = g_zpart[(size_t)r0*ldc + col + 1]   + 0.3f*v1;
                v2 = g_zpart[(size_t)(r0+8)*ldc + col]   + 0.3f*v2;
                v3 = g_zpart[(size_t)(r0+8)*ldc + col+1] + 0.3f*v3;
            }
            *(float2*)(C + (size_t)r0*ldc + col)     = make_float2(v0, v1);
            *(float2*)(C + (size_t)(r0+8)*ldc + col) = make_float2(v2, v3);
        }
    }
}

// ---------------- permute weffT chunks into fragment layout ----------------
__global__ void k_permW()
{
    int bx = blockIdx.x;
    int k = bx >> 4, rem = bx & 15, bnb = rem >> 3, c8 = rem & 7;
    int tid = threadIdx.x;
    const float* src = g_weffT + (size_t)k*65536;
    float* dst = g_weffP + ((size_t)(k*2 + bnb)*8 + c8)*4096;
    #pragma unroll
    for (int q = 0; q < 4; q++) {
        int f = tid + q*256;
        int row = f >> 3, seg = f & 7;
        float4 v = *(const float4*)(src + (size_t)(bnb*128 + row)*256 + c8*32 + seg*4);
        int ks = seg >> 1, posK = seg & 1;
        int bbase = (((row >> 3)*4 + ks)*32 + (row & 7)*4)*2 + posK;
        float bv[4] = {v.x, v.y, v.z, v.w};
        #pragma unroll
        for (int e = 0; e < 4; e++) dst[bbase + e*2] = tf32r(bv[e]);
    }
}

// ---------------- permute wp1T halves into fragment layout -----------------
__global__ void k_permP()
{
    int bx = blockIdx.x;
    int k = bx >> 1, h = bx & 1;
    int tid = threadIdx.x;
    const float* src = g_wp1T + (size_t)k*8192;
    float* dst = g_wp1P + (size_t)(k*2 + h)*4096;
    #pragma unroll
    for (int q = 0; q < 4; q++) {
        int f = tid + q*256;
        int row = f >> 3, seg = f & 7;
        float4 v = *(const float4*)(src + (size_t)(h*128 + row)*32 + seg*4);
        int ks = seg >> 1, posK = seg & 1;
        int bbase = (((row >> 3)*4 + ks)*32 + (row & 7)*4)*2 + posK;
        float bv[4] = {v.x, v.y, v.z, v.w};
        #pragma unroll
        for (int e = 0; e < 4; e++) dst[bbase + e*2] = tf32r(bv[e]);
    }
}

// ---------------- fully fused (M=64 tiles, 2 CTAs/SM):
// hf1 = gelu(Σ_k gelu(xc_k@wp1T_k^T + ckb)@weffT_k + bconst)
__global__ void __launch_bounds__(256, 2) k_ff()
{
    extern __shared__ float smem[];
    float* saA = smem;             // 4 chunks x 2048 (A-fragments of 64-row p1 half)
    float* sxc = smem + 8192;      // 2048 (xc A-chunk, 64x32)
    float* swp = smem + 10240;     // 8192 (wp1P halves)
    float* swf = smem + 18432;     // 8192 (weffP chunks, dbl buf)
    int bm = blockIdx.y*64, bnb = blockIdx.x, bn = bnb*128;
    int b  = bm >> 10;
    int tid = threadIdx.x, wid = tid >> 5, lane = tid & 31;
    int g = lane >> 2, tig = lane & 3;
    int wm = (wid & 3)*16, wn = (wid >> 2)*64;
    uint32_t swp_u = smem_u32(swp), swf_u = smem_u32(swf);

    float ACC[8][4];
    #pragma unroll
    for (int j = 0; j < 8; j++)
        #pragma unroll
        for (int q = 0; q < 4; q++) ACC[j][q] = 0.f;

    // chunk t = k*8 + h*4 + cc, buffer t&1
    auto issue_chunk = [&](int t) {
        const float* src = g_weffP + ((size_t)((t >> 3)*2 + bnb)*8 + (t & 7))*4096 + tid*16;
        uint32_t dst = swf_u + ((uint32_t)(t & 1)*4096 + tid*16)*4;
        #pragma unroll
        for (int q = 0; q < 4; q++) CP_ASYNC16(dst + q*16, src + q*4);
    };
    auto issue_swp = [&](int k) {
        const float* src = g_wp1P + (size_t)k*8192 + tid*32;
        uint32_t dst = swp_u + (uint32_t)tid*32*4;
        #pragma unroll
        for (int q = 0; q < 8; q++) CP_ASYNC16(dst + q*16, src + q*4);
    };

    issue_swp(0);
    issue_chunk(0);
    CP_COMMIT();

    int t = 0;
    const int TMAX = KF*8;
    for (int k = 0; k < KF; k++) {
        __syncthreads();     // sxc readers (gemm1 of k-1) done
        // xc A-chunk scatter: 64 rows x 32 cols = 512 float4, 2 per thread
        {
            const float* Axc = g_xc + ((size_t)k*RTOT + bm)*32;
            #pragma unroll
            for (int q = 0; q < 2; q++) {
                int f = tid + q*256;
                int row = f >> 3, seg = f & 7;
                float4 v = *(const float4*)(Axc + (size_t)row*32 + seg*4);
                int ks = seg >> 1, posK = seg & 1;
                int abase = (((row >> 4)*4 + ks)*32 + (row & 7)*4)*4 + posK*2 + ((row >> 3) & 1);
                float av[4] = {v.x, v.y, v.z, v.w};
                #pragma unroll
                for (int e = 0; e < 4; e++) sxc[abase + e*4] = tf32r(av[e]);
            }
        }
        CP_WAIT0();
        __syncthreads();     // swp(k), chunk t, sxc all visible
        #pragma unroll
        for (int h = 0; h < 2; h++) {
            // GEMM1: p1 half (64 x 128) = xc @ wp1T_h
            float a1[8][4];
            #pragma unroll
            for (int j = 0; j < 8; j++)
                #pragma unroll
                for (int q = 0; q < 4; q++) a1[j][q] = 0.f;
            gmma64(sxc, swp + h*4096, wid, lane, a1);
            __syncthreads();   // saA readers (prev chunks' gmma) done
            const float* ck = g_ckb + (size_t)(k*BB + b)*DD + h*128;
            #pragma unroll
            for (int j = 0; j < 8; j++)
                #pragma unroll
                for (int q = 0; q < 4; q++) {
                    int row  = wm + g + ((q >> 1) ? 8 : 0);
                    int kcol = wn + j*8 + tig*2 + (q & 1);
                    float val = gelu_f(a1[j][q] + ck[kcol]);
                    int cc = kcol >> 5, kk = kcol & 31;
                    int idx = cc*2048
                            + (((row >> 4)*4 + (kk >> 3))*32 + (row & 7)*4 + (kk & 3))*4
                            + ((kk >> 2) & 1)*2 + ((row >> 3) & 1);
                    saA[idx] = tf32r(val);
                }
            __syncthreads();   // saA visible
            #pragma unroll
            for (int cc = 0; cc < 4; cc++) {
                if (cc > 0 || h > 0) {
                    CP_WAIT0();
                    __syncthreads();   // chunk t visible; prior gmma done
                }
                bool iss = false;
                if (t + 1 < TMAX) { issue_chunk(t + 1); iss = true; }
                if ((t & 7) == 6 && k + 1 < KF) { issue_swp(k + 1); iss = true; }
                if (iss) CP_COMMIT();
                gmma64(saA + cc*2048, swf + (t & 1)*4096, wid, lane, ACC);
                t++;
            }
        }
    }

    // epilogue: 64 rows
    {
        int r0 = bm + wm + g;
        #pragma unroll
        for (int j = 0; j < 8; j++) {
            int col = bn + wn + j*8 + tig*2;
            float b0 = g_bconst[col], b1 = g_bconst[col+1];
            float2 lo = make_float2(gelu_f(ACC[j][0] + b0), gelu_f(ACC[j][1] + b1));
            float2 hi = make_float2(gelu_f(ACC[j][2] + b0), gelu_f(ACC[j][3] + b1));
            *(float2*)(g_hf1 + (size_t)r0*256 + col)     = lo;
            *(float2*)(g_hf1 + (size_t)(r0+8)*256 + col) = hi;
        }
    }
}

// ---------------- weight transpose [K,N] -> [N,K] --------------------------
__global__ void k_tr(const float* __restrict__ W, float* __restrict__ WT, int K, int N)
{
    __shared__ float tile[32][33];
    int z = blockIdx.z;
    W  += (size_t)z*K*N;
    WT += (size_t)z*K*N;
    int k0 = blockIdx.y*32, n0 = blockIdx.x*32;
    int tx = threadIdx.x, ty = threadIdx.y;
    for (int i = ty; i < 32; i += 8) tile[i][tx] = W[(size_t)(k0+i)*N + n0+tx];
    __syncthreads();
    for (int i = ty; i < 32; i += 8) WT[(size_t)(n0+i)*K + k0+tx] = tile[tx][i];
}

// ---------------- k_uv partials: wp1 fold, split over e ---------------------
__global__ void k_uv1(const float* __restrict__ W, const float* __restrict__ W1)
{
    int bx = blockIdx.x;
    int k = bx >> 2, eq = bx & 3;
    int o = threadIdx.x;
    __shared__ float Ws[CC*DD];
    for (int i = o; i < CC*DD; i += 256) Ws[i] = W[i];
    __syncthreads();
    float acc[32];
    #pragma unroll
    for (int c = 0; c < 32; c++) acc[c] = 0.f;
    const float* w1 = W1 + (size_t)k*512*DD;
    for (int e = eq*64; e < eq*64 + 64; e++) {
        float u = w1[(size_t)e*DD + o];
        float v = w1[(size_t)(256+e)*DD + o];
        #pragma unroll
        for (int c = 0; c < 16; c++) {
            acc[c]      += Ws[c*DD + e]*u;
            acc[16 + c] += Ws[c*DD + e]*v;
        }
    }
    float* dst = g_uvp + ((size_t)(k*4 + eq)*DD + o)*32;
    #pragma unroll
    for (int c = 0; c < 32; c++) dst[c] = acc[c];
}
__global__ void k_uv2()
{
    int k = blockIdx.x, o = threadIdx.x;
    float* dst = g_wp1T + ((size_t)k*DD + o)*32;
    #pragma unroll
    for (int c = 0; c < 32; c++) {
        float s = 0.f;
        #pragma unroll
        for (int eq = 0; eq < 4; eq++)
            s += g_uvp[((size_t)(k*4 + eq)*DD + o)*32 + c];
        dst[c] = s;
    }
}

// ---------------- te DFT + te_att ------------------------------------------
__global__ void k_tedft(const float* __restrict__ in_proj_b)
{
    int b = blockIdx.x, e = threadIdx.x;
    float teb[PP];
    #pragma unroll
    for (int p = 0; p < PP; p++)
        teb[p] = g_time_emb[(b*PP + p)*DD + e] + in_proj_b[e];
    float ta = 0.f;
    #pragma unroll
    for (int p = 0; p < PP; p++) ta += g_att[b*PP + p]*teb[p];
    g_teatt[b*DD + e] = ta;
    for (int k = 0; k < KF; k++) {
        float re = 0.f, im = 0.f;
        #pragma unroll
        for (int p = 0; p < PP; p++) {
            re += teb[p]*g_tw[k*PP + p];
            im -= teb[p]*g_tw[KF*PP + k*PP + p];
        }
        g_tere[(k*BB + b)*DD + e] = re;
        g_teim[(k*BB + b)*DD + e] = im;
    }
}

// ---------------- c_kb[o] = b1_k[o] + Σ_e tere*W1_k[e][o] + teim*W1_k[256+e][o]
__global__ void k_ckb(const float* __restrict__ W1, const float* __restrict__ b1)
{
    int k = blockIdx.x, b = blockIdx.y, o = threadIdx.x;
    __shared__ float sre[DD], sim[DD];
    sre[o] = g_tere[(k*BB + b)*DD + o];
    sim[o] = g_teim[(k*BB + b)*DD + o];
    __syncthreads();
    float acc = b1[(size_t)k*DD + o];
    const float* w1 = W1 + (size_t)k*512*DD;
    for (int e = 0; e < 256; e++)
        acc += sre[e]*w1[(size_t)e*DD + o] + sim[e]*w1[(size_t)(256+e)*DD + o];
    g_ckb[(k*BB + b)*DD + o] = acc;
}

// ---------------- folded bias: bconst = comb_b1 + Σ b2·Wc1 (two-stage) -----
__global__ void k_bc1(const float* __restrict__ sfe_b2,
                      const float* __restrict__ comb_w1)
{
    int k = blockIdx.x, j = threadIdx.x;
    float s = 0.f;
    for (int i = k*256; i < k*256 + 256; i++)
        s += sfe_b2[i]*comb_w1[(size_t)i*256 + j];
    g_bcp[k*DD + j] = s;
}
__global__ void k_bc2(const float* __restrict__ comb_b1)
{
    int j = threadIdx.x;
    float s = comb_b1[j];
    #pragma unroll
    for (int k = 0; k < KF; k++) s += g_bcp[k*DD + j];
    g_bconst[j] = s;
}

// ---------------- tiny init ------------------------------------------------
__global__ void k_init(const float* __restrict__ pe_w1, const float* __restrict__ pe_b1,
                       const float* __restrict__ pe_w2, const float* __restrict__ pe_b2,
                       const float* __restrict__ pool_param)
{
    int t = threadIdx.x;
    for (int idx = t; idx < KF*PP; idx += blockDim.x) {
        int k = idx / PP, p = idx % PP;
        double ang = 2.0*M_PI*(double)(k*p)/24.0;
        g_tw[idx]        = (float)cos(ang);
        g_tw[KF*PP+idx]  = (float)sin(ang);
    }
    if (t < 2*PP) {
        int kk = t / PP, p = t % PP;
        double period = (kk == 0) ? 24.0 : 72.0;
        double ph = 2.0*M_PI*(double)p/period;
        float s = (float)sin(ph), c = (float)cos(ph);
        float hid[64];
        #pragma unroll
        for (int o = 0; o < 64; o++) {
            float v = s*pe_w1[kk*128 + o] + c*pe_w1[kk*128 + 64 + o] + pe_b1[kk*64 + o];
            hid[o] = gelu_f(v);
        }
        for (int q = 0; q < 64; q++) {
            float acc = pe_b2[kk*64 + q];
            #pragma unroll
            for (int o = 0; o < 64; o++) acc += hid[o]*pe_w2[kk*4096 + o*64 + q];
            g_periodic[p*128 + kk*64 + q] = acc;
        }
    }
    if (t == 0) {
        float mx = -1e30f;
        for (int p = 0; p < PP; p++) mx = fmaxf(mx, pool_param[p]);
        float se = 0.f, e[PP];
        for (int p = 0; p < PP; p++) { e[p] = expf(pool_param[p]-mx); se += e[p]; }
        for (int p = 0; p < PP; p++) g_base_att[p] = e[p]/se;
    }
}

// ---------------- spatial mean -> noise; assemble time_emb ----------------
__global__ void k_noise(const float* __restrict__ x, const float* __restrict__ noise_w,
                        const float* __restrict__ noise_b)
{
    int bp = blockIdx.x;
    int t  = threadIdx.x;
    __shared__ float partial[256];
    __shared__ float mean[CC];
    const float* xb = x + (size_t)bp*NN*CC;
    float acc = 0.f;
    for (int i = t; i < NN*CC; i += 256) acc += xb[i];
    partial[t] = acc;
    __syncthreads();
    if (t < CC) {
        float s = 0.f;
        for (int j = t; j < 256; j += CC) s += partial[j];
        mean[t] = s*(1.f/(float)NN);
    }
    __syncthreads();
    if (t < 128) {
        float nz = noise_b[t];
        #pragma unroll
        for (int c = 0; c < CC; c++) nz += mean[c]*noise_w[c*128 + t];
        g_time_emb[bp*DD + 128 + t] = nz;
        g_time_emb[bp*DD + t]       = g_periodic[(bp % PP)*128 + t];
    }
}

__global__ void k_timevec(float* __restrict__ out)
{
    int b = blockIdx.x, e = threadIdx.x;
    float s = 0.f;
    for (int p = 0; p < PP; p++) s += g_time_emb[(b*PP + p)*DD + e];
    out[(size_t)BB*NN*DD + b*DD + e] = s*(1.f/24.f);
}

// ---------------- x DFT + attention-weighted x -----------------------------
__global__ void __launch_bounds__(256) k_xdft(const float* __restrict__ x)
{
    __shared__ float twc[KF*PP], tws[KF*PP], atts[PP];
    int tid = threadIdx.x;
    int r = blockIdx.x*16 + (tid >> 4);
    int c = tid & 15;
    int b = r >> 10, n = r & 1023;
    for (int i = tid; i < KF*PP; i += 256) { twc[i] = g_tw[i]; tws[i] = g_tw[KF*PP + i]; }
    if (tid < PP) atts[tid] = g_att[b*PP + tid];
    __syncthreads();
    float re[KF], im[KF], xa = 0.f;
    #pragma unroll
    for (int k = 0; k < KF; k++) { re[k] = 0.f; im[k] = 0.f; }
    #pragma unroll
    for (int p = 0; p < PP; p++) {
        float xv = x[((size_t)(b*PP + p)*NN + n)*CC + c];
        xa += atts[p]*xv;
        #pragma unroll
        for (int k = 0; k < KF; k++) {
            re[k] += twc[k*PP + p]*xv;
            im[k] -= tws[k*PP + p]*xv;
        }
    }
    g_xatt[(size_t)r*CC + c] = xa;
    #pragma unroll
    for (int k = 0; k < KF; k++) {
        g_xc[((size_t)k*RTOT + r)*32 + c]      = re[k];
        g_xc[((size_t)k*RTOT + r)*32 + 16 + c] = im[k];
    }
}

// ---------------- zpart = xatt @ W + te_att --------------------------------
__global__ void k_zpart(const float* __restrict__ w)
{
    int blk = blockIdx.x;
    int r0 = blk*64;
    int b = r0 >> 10;
    int t = threadIdx.x;
    __shared__ float Ws[CC*DD];
    __shared__ float xs[64*CC];
    __shared__ float tb[DD];
    for (int i = t; i < CC*DD; i += 256) Ws[i] = w[i];
    tb[t] = g_teatt[b*DD + t];
    for (int i = t; i < 64*CC; i += 256) xs[i] = g_xatt[(size_t)r0*CC + i];
    __syncthreads();
    float* zp = g_zpart + (size_t)r0*DD;
    for (int nn = 0; nn < 64; nn++) {
        float acc = tb[t];
        #pragma unroll
        for (int c = 0; c < CC; c++) acc += xs[nn*CC + c]*Ws[c*DD + t];
        zp[(size_t)nn*DD + t] = acc;
    }
}

// ---------------- gating: lagged diffs over raw x -------------------------
__device__ __forceinline__ float xr_val(const float* __restrict__ xb, int p, int i)
{
    float xp = xb[(size_t)p*16384 + i];
    float base;
    if (p <= 1) base = xb[i];
    else base = (xb[(size_t)(p-2)*16384 + i] + xb[(size_t)(p-1)*16384 + i] + xp)*(1.f/3.f);
    return xp - base;
}

__global__ void k_gd(const float* __restrict__ x)
{
    int bp = blockIdx.x;
    int b = bp / PP, p = bp % PP;
    int t = threadIdx.x;
    const float* xb = x + (size_t)b*PP*16384;
    float s0=0.f, s1=0.f, s2=0.f, s3=0.f;
    for (int i = t; i < 16384; i += 256) {
        float xr_p = xr_val(xb, p, i);
        if (p >= 1) s0 += fabsf(xr_p - xr_val(xb, p-1, i));
        if (p >= 2) s1 += fabsf(xr_p - xr_val(xb, p-2, i));
        if (p >= 4) s2 += fabsf(xr_p - xr_val(xb, p-4, i));
        if (p >= 6) s3 += fabsf(xr_p - xr_val(xb, p-6, i));
    }
    __shared__ float red[4][256];
    red[0][t]=s0; red[1][t]=s1; red[2][t]=s2; red[3][t]=s3;
    __syncthreads();
    if (t < 4) {
        float ss = 0.f;
        for (int j = 0; j < 256; j++) ss += red[t][j];
        g_dd[(b*4 + t)*PP + p] = ss*(1.f/16384.f);
    }
}

__global__ void k_att()
{
    __shared__ float sp[BB][4][PP];
    int t = threadIdx.x;
    if (t < 32) {
        int b = t >> 2, l = t & 3;
        float dv[PP], srt[PP];
        for (int p = 0; p < PP; p++) dv[p] = g_dd[(b*4 + l)*PP + p];
        for (int p = 0; p < PP; p++) srt[p] = dv[p];
        isort(srt, PP);
        float med = srt[11];
        for (int p = 0; p < PP; p++) srt[p] = fabsf(dv[p] - med);
        isort(srt, PP);
        float mad = srt[11];
        float denom = mad*1.4826f + 1e-6f;
        for (int p = 0; p < PP; p++) {
            float zz = (dv[p] - med)/denom;
            sp[b][l][p] = softplus_f(zz);
        }
    }
    __syncthreads();
    if (t < BB) {
        int b = t;
        float g[PP];
        for (int p = 0; p < PP; p++)
            g[p] = 0.25f*(sp[b][0][p] + sp[b][1][p] + sp[b][2][p] + sp[b][3][p]);
        float c = g[0];
        for (int p = 1; p < PP; p++) { c = 0.6f*c + 0.4f*g[p]; g[p] = c; }
        float gm = 0.f;
        for (int p = 0; p < PP; p++) gm += g[p];
        gm *= (1.f/24.f);
        float logit[PP], mx = -1e30f;
        for (int p = 0; p < PP; p++) {
            float gg = 1.f/(1.f + expf(-1.5f*(g[p] - gm)));
            logit[p] = g_base_att[p]*(1.f + gg);
            mx = fmaxf(mx, logit[p]);
        }
        float se = 0.f;
        for (int p = 0; p < PP; p++) { logit[p] = expf(logit[p] - mx); se += logit[p]; }
        for (int p = 0; p < PP; p++) g_att[b*PP + p] = logit[p]/se;
    }
}

// ---------------- launch ---------------------------------------------------
extern "C" void kernel_launch(void* const* d_in, const int* in_sizes, int n_in,
                              void* d_out, int out_size)
{
    const float* x         = (const float*)d_in[0];
    const float* in_proj_w = (const float*)d_in[1];
    const float* in_proj_b = (const float*)d_in[2];
    const float* pe_w1     = (const float*)d_in[3];
    const float* pe_b1     = (const float*)d_in[4];
    const float* pe_w2     = (const float*)d_in[5];
    const float* pe_b2     = (const float*)d_in[6];
    const float* noise_w   = (const float*)d_in[7];
    const float* noise_b   = (const float*)d_in[8];
    const float* sfe_w1    = (const float*)d_in[9];
    const float* sfe_b1    = (const float*)d_in[10];
    const float* sfe_w2    = (const float*)d_in[11];
    const float* sfe_b2    = (const float*)d_in[12];
    const float* comb_w1   = (const float*)d_in[13];
    const float* comb_b1   = (const float*)d_in[14];
    const float* comb_w2   = (const float*)d_in[15];
    const float* comb_b2   = (const float*)d_in[16];
    const float* pool_param= (const float*)d_in[17];
    float* out = (float*)d_out;

    float *p_hf1, *p_wc1T, *p_weffT, *p_wc2T, *p_zero;
    cudaGetSymbolAddress((void**)&p_hf1,   g_hf1);
    cudaGetSymbolAddress((void**)&p_wc1T,  g_wc1T);
    cudaGetSymbolAddress((void**)&p_weffT, g_weffT);
    cudaGetSymbolAddress((void**)&p_wc2T,  g_wc2T);
    cudaGetSymbolAddress((void**)&p_zero,  g_zero);

    const int SMEM  = 16384*4;     // 64 KB for k_mma
    const int SMEMF = 26624*4;     // 104 KB for k_ff (2 CTAs/SM)
    cudaFuncSetAttribute(k_mma<0,0>, cudaFuncAttributeMaxDynamicSharedMemorySize, SMEM);
    cudaFuncSetAttribute(k_mma<0,1>, cudaFuncAttributeMaxDynamicSharedMemorySize, SMEM);
    cudaFuncSetAttribute(k_ff,       cudaFuncAttributeMaxDynamicSharedMemorySize, SMEMF);

    // scalars / gating / embeddings
    k_init<<<1, 256>>>(pe_w1, pe_b1, pe_w2, pe_b2, pool_param);
    k_gd<<<BB*PP, 256>>>(x);
    k_att<<<1, 32>>>();
    k_noise<<<BB*PP, 256>>>(x, noise_w, noise_b);
    k_tedft<<<BB, 256>>>(in_proj_b);
    k_timevec<<<BB, 256>>>(out);

    // x-side folds
    k_xdft<<<RTOT/16, 256>>>(x);
    k_zpart<<<RTOT/64, 256>>>(in_proj_w);

    // weight prep
    dim3 trb(32, 8);
    k_uv1<<<KF*4, 256>>>(in_proj_w, sfe_w1);
    k_uv2<<<KF, 256>>>();
    k_ckb<<<dim3(KF, BB), 256>>>(sfe_w1, sfe_b1);
    k_tr<<<dim3(256/32, 256/32, KF), trb>>>(comb_w1, p_wc1T, 256, 256);
    k_tr<<<dim3(256/32, 256/32, 1),  trb>>>(comb_w2, p_wc2T, 256, 256);
    k_mma<0,0><<<dim3(2, 2, KF), 256, SMEM>>>(p_wc1T, sfe_w2, p_zero, p_weffT,
        256, 256, 65536L, 65536L, 0L, 65536L, 0);
    k_permW<<<KF*16, 256>>>();
    k_permP<<<KF*2, 256>>>();
    k_bc1<<<KF, 256>>>(sfe_b2, comb_w1);
    k_bc2<<<1, 256>>>(comb_b1);

    // fused sfe1 + sfe2·comb1: hf1
    k_ff<<<dim3(2, 128), 256, SMEMF>>>();
    // out = zpart + 0.3*(hf1 @ Wc2 + b2)
    k_mma<0,1><<<dim3(2, 64), 256, SMEM>>>(p_hf1, p_wc2T, comb_b2, out,
        256, 256, 0L, 0L, 0L, 0L, 0);
}

// round 16
// speedup vs baseline: 1.3024x; 1.3024x over previous
#include <cuda_runtime.h>
#include <cstdint>
#include <math.h>

#define BB 8
#define PP 24
#define CC 16
#define DD 256
#define NN 1024
#define KF 13
#define RTOT (BB*NN)      // 8192

// ---------------- scratch (device globals; no allocations) ----------------
__device__ __align__(128) float g_xc[(size_t)KF*RTOT*32];   // per-k [re(16)|im(16)]
__device__ __align__(128) float g_xatt[RTOT*CC];
__device__ __align__(128) float g_hf1[RTOT*DD];
__device__ __align__(128) float g_zpart[RTOT*DD];
__device__ __align__(128) float g_time_emb[BB*PP*DD];
__device__ __align__(128) float g_periodic[PP*128];
__device__ float g_base_att[PP];
__device__ float g_att[BB*PP];
__device__ float g_dd[BB*4*PP];
__device__ float g_tw[2*KF*PP];
__device__ float g_zero[DD];
__device__ float g_bconst[DD];
__device__ float g_bcp[KF*DD];
__device__ __align__(128) float g_tere[KF*BB*DD];
__device__ __align__(128) float g_teim[KF*BB*DD];
__device__ __align__(128) float g_teatt[BB*DD];
__device__ __align__(128) float g_ckb[KF*BB*DD];
// derived weights
__device__ __align__(128) float g_wp1T[KF*DD*32];      // [(k,o),32] = W@W1 fold, K-major
__device__ __align__(128) float g_uvp[KF*4*DD*32];     // k_uv partials
__device__ __align__(128) float g_wc1T[KF*DD*DD];
__device__ __align__(128) float g_weffT[KF*DD*DD];
__device__ __align__(128) float g_wc2T[DD*DD];
// bf16 fragment-permuted copies for k_ff (packed bf16x2 words)
__device__ __align__(128) uint32_t g_weffP[(size_t)KF*2*8*2048];
__device__ __align__(128) uint32_t g_wp1P[KF*2*2048];

__device__ __forceinline__ float gelu_f(float v) {
    return 0.5f*v*(1.f + erff(v*0.70710678118654752f));
}
__device__ __forceinline__ float softplus_f(float v) {
    return fmaxf(v, 0.f) + log1pf(expf(-fabsf(v)));
}
__device__ void isort(float* a, int n) {
    for (int i = 1; i < n; i++) {
        float v = a[i]; int j = i-1;
        while (j >= 0 && a[j] > v) { a[j+1] = a[j]; j--; }
        a[j+1] = v;
    }
}
__device__ __forceinline__ float tf32r(float x) {
    uint32_t r;
    asm("cvt.rna.tf32.f32 %0, %1;" : "=r"(r) : "f"(x));
    return __uint_as_float(r);
}
__device__ __forceinline__ uint32_t pack_bf16(float lo, float hi) {
    uint32_t r;
    asm("cvt.rn.bf16x2.f32 %0, %1, %2;" : "=r"(r) : "f"(hi), "f"(lo));
    return r;
}
__device__ __forceinline__ uint32_t smem_u32(const void* p) {
    uint32_t a;
    asm("{ .reg .u64 t; cvta.to.shared.u64 t, %1; cvt.u32.u64 %0, t; }" : "=r"(a) : "l"(p));
    return a;
}
#define CP_ASYNC16(smaddr, gptr) \
    asm volatile("cp.async.ca.shared.global [%0], [%1], 16;" :: "r"(smaddr), "l"(gptr))
#define CP_COMMIT() asm volatile("cp.async.commit_group;" ::: "memory")
#define CP_WAIT0()  asm volatile("cp.async.wait_group 0;" ::: "memory")

// ---------------- warp mma --------------------------------------------------
__device__ __forceinline__ void mma_tf32(float* d, const float4& a, const float2& b) {
    asm volatile("mma.sync.aligned.m16n8k8.row.col.f32.tf32.tf32.f32 "
        "{%0,%1,%2,%3}, {%4,%5,%6,%7}, {%8,%9}, {%0,%1,%2,%3};"
        : "+f"(d[0]), "+f"(d[1]), "+f"(d[2]), "+f"(d[3])
        : "r"(__float_as_uint(a.x)), "r"(__float_as_uint(a.y)),
          "r"(__float_as_uint(a.z)), "r"(__float_as_uint(a.w)),
          "r"(__float_as_uint(b.x)), "r"(__float_as_uint(b.y)));
}
__device__ __forceinline__ void mma_bf16(float* d, const uint32_t* a, const uint32_t* b) {
    asm volatile("mma.sync.aligned.m16n8k16.row.col.f32.bf16.bf16.f32 "
        "{%0,%1,%2,%3}, {%4,%5,%6,%7}, {%8,%9}, {%0,%1,%2,%3};"
        : "+f"(d[0]), "+f"(d[1]), "+f"(d[2]), "+f"(d[3])
        : "r"(a[0]), "r"(a[1]), "r"(a[2]), "r"(a[3]), "r"(b[0]), "r"(b[1]));
}

// tf32 GEMM building blocks (CTA tile 128x128, 8 warps, K-chunk 32) -- k_mma
__device__ __forceinline__ void gload(const float* A, const float* Wt, int bm, int bn,
                                      int K, int koff, int tid, float4* ra, float4* rb)
{
    #pragma unroll
    for (int q = 0; q < 4; q++) {
        int f = tid + q*256;
        int row = f >> 3, seg = f & 7;
        ra[q] = *(const float4*)(A  + (size_t)(bm + row)*K + koff + seg*4);
        rb[q] = *(const float4*)(Wt + (size_t)(bn + row)*K + koff + seg*4);
    }
}
__device__ __forceinline__ void gscatter(const float4* ra, const float4* rb,
                                         float* sa, float* sb, int tid)
{
    #pragma unroll
    for (int q = 0; q < 4; q++) {
        int f = tid + q*256;
        int row = f >> 3, seg = f & 7;
        int ks = seg >> 1, posK = seg & 1;
        int mt = row >> 4, posM = (row >> 3) & 1, gga = row & 7;
        int abase = ((mt*4 + ks)*32 + gga*4)*4 + posK*2 + posM;
        float av[4] = {ra[q].x, ra[q].y, ra[q].z, ra[q].w};
        #pragma unroll
        for (int e = 0; e < 4; e++) sa[abase + e*4] = tf32r(av[e]);
        int nt = row >> 3, ggb = row & 7;
        int bbase = ((nt*4 + ks)*32 + ggb*4)*2 + posK;
        float bv[4] = {rb[q].x, rb[q].y, rb[q].z, rb[q].w};
        #pragma unroll
        for (int e = 0; e < 4; e++) sb[bbase + e*2] = tf32r(bv[e]);
    }
}
__device__ __forceinline__ void gmma(const float* sa, const float* sb,
                                     int wid, int lane, float acc[2][8][4])
{
    #pragma unroll
    for (int ks = 0; ks < 4; ks++) {
        float4 af[2];
        #pragma unroll
        for (int i = 0; i < 2; i++) {
            int mt = (wid & 3)*2 + i;
            af[i] = *(const float4*)&sa[((mt*4 + ks)*32 + lane)*4];
        }
        float2 bf[8];
        #pragma unroll
        for (int j = 0; j < 8; j++) {
            int nt = (wid >> 2)*8 + j;
            bf[j] = *(const float2*)&sb[((nt*4 + ks)*32 + lane)*2];
        }
        #pragma unroll
        for (int i = 0; i < 2; i++)
            #pragma unroll
            for (int j = 0; j < 8; j++)
                mma_tf32(acc[i][j], af[i], bf[j]);
    }
}

// ---------------- generic tf32 GEMM: C = act(A @ Wt^T + bias) --------------
template<int ACT, int FIN>
__global__ void __launch_bounds__(256) k_mma(
    const float* __restrict__ A, const float* __restrict__ Wt,
    const float* __restrict__ bias, float* __restrict__ C,
    int K, int ldc, long sA, long sW, long sB, long sC, int bstride)
{
    extern __shared__ float smem[];
    float* sa0 = smem;         float* sa1 = smem + 4096;
    float* sb0 = smem + 8192;  float* sb1 = smem + 12288;
    int z = blockIdx.z;
    int bm = blockIdx.y*128, bn = blockIdx.x*128;
    A    += (size_t)z*sA;
    Wt   += (size_t)z*sW;
    bias += (size_t)z*sB + (size_t)(bm >> 10)*bstride;
    C    += (size_t)z*sC;
    int tid = threadIdx.x, wid = tid >> 5, lane = tid & 31;
    int g = lane >> 2, tig = lane & 3;
    int wm = (wid & 3)*32, wn = (wid >> 2)*64;

    float acc[2][8][4];
    #pragma unroll
    for (int i = 0; i < 2; i++)
        #pragma unroll
        for (int j = 0; j < 8; j++)
            #pragma unroll
            for (int q = 0; q < 4; q++) acc[i][j][q] = 0.f;

    int nch = K >> 5;
    float4 ra[4], rb[4];
    gload(A, Wt, bm, bn, K, 0, tid, ra, rb);
    gscatter(ra, rb, sa0, sb0, tid);
    __syncthreads();
    for (int c = 0; c < nch; c++) {
        int buf = c & 1;
        if (c + 1 < nch) gload(A, Wt, bm, bn, K, (c+1)*32, tid, ra, rb);
        gmma(buf ? sa1 : sa0, buf ? sb1 : sb0, wid, lane, acc);
        if (c + 1 < nch) gscatter(ra, rb, buf ? sa0 : sa1, buf ? sb0 : sb1, tid);
        __syncthreads();
    }

    #pragma unroll
    for (int i = 0; i < 2; i++) {
        int r0 = bm + wm + i*16 + g;
        #pragma unroll
        for (int j = 0; j < 8; j++) {
            int col = bn + wn + j*8 + tig*2;
            float b0 = bias[col], b1 = bias[col+1];
            float v0 = acc[i][j][0] + b0, v1 = acc[i][j][1] + b1;
            float v2 = acc[i][j][2] + b0, v3 = acc[i][j][3] + b1;
            if (ACT) { v0 = gelu_f(v0); v1 = gelu_f(v1); v2 = gelu_f(v2); v3 = gelu_f(v3); }
            if (FIN) {
                v0 = g_zpart[(size_t)r0*ldc + col]       + 0.3f*v0;
                v1 = g_zpart[(size_t)r0*ldc + col + 1]   + 0.3f*v1;
                v2 = g_zpart[(size_t)(r0+8)*ldc + col]   + 0.3f*v2;
                v3 = g_zpart[(size_t)(r0+8)*ldc + col+1] + 0.3f*v3;
            }
            *(float2*)(C + (size_t)r0*ldc + col)     = make_float2(v0, v1);
            *(float2*)(C + (size_t)(r0+8)*ldc + col) = make_float2(v2, v3);
        }
    }
}

// ---------------- permute weffT chunks into bf16 B-fragment layout ---------
// B layout per 128x32 chunk: [tile(nt*2+kstep)][lane(col g=n&7, tig from kk)][w]
__global__ void k_permW()
{
    int bx = blockIdx.x;            // KF*16
    int k = bx >> 4, rem = bx & 15, bnb = rem >> 3, c8 = rem & 7;
    int tid = threadIdx.x;
    const float* src = g_weffT + (size_t)k*65536 + (size_t)bnb*128*256 + c8*32;
    uint32_t* dst = g_weffP + ((size_t)(k*2 + bnb)*8 + c8)*2048;
    #pragma unroll
    for (int q = 0; q < 8; q++) {
        int widx = tid + q*256;
        int tile = widx >> 6, lanep = (widx >> 1) & 31, w = widx & 1;
        int nt = tile >> 1, kstep = tile & 1;
        int gp = lanep >> 2, tigp = lanep & 3;
        int n = nt*8 + gp;
        int kk = kstep*16 + w*8 + tigp*2;
        float2 v = *(const float2*)(src + (size_t)n*256 + kk);
        dst[widx] = pack_bf16(v.x, v.y);
    }
}

// ---------------- permute wp1T halves into bf16 B-fragment layout ----------
__global__ void k_permP()
{
    int bx = blockIdx.x;            // KF*2
    int k = bx >> 1, h = bx & 1;
    int tid = threadIdx.x;
    const float* src = g_wp1T + (size_t)k*8192 + (size_t)h*128*32;
    uint32_t* dst = g_wp1P + (size_t)(k*2 + h)*2048;
    #pragma unroll
    for (int q = 0; q < 8; q++) {
        int widx = tid + q*256;
        int tile = widx >> 6, lanep = (widx >> 1) & 31, w = widx & 1;
        int nt = tile >> 1, kstep = tile & 1;
        int gp = lanep >> 2, tigp = lanep & 3;
        int o = nt*8 + gp;
        int c = kstep*16 + w*8 + tigp*2;
        float2 v = *(const float2*)(src + (size_t)o*32 + c);
        dst[widx] = pack_bf16(v.x, v.y);
    }
}

// ---------------- fully fused bf16 m16n8k16 (M=128, 1 CTA/SM):
// hf1 = gelu(Σ_k gelu(xc_k@wp1T_k^T + ckb)@weffT_k + bconst)
__global__ void __launch_bounds__(256) k_ff()
{
    extern __shared__ uint32_t smu[];
    uint32_t* saA = smu;            // 4 chunks x 2048 (A-fragments of p1 half)
    uint32_t* sxc = smu + 8192;     // 2048 (xc A-chunk 128x32)
    uint32_t* swp = smu + 10240;    // 2 x 2048 (wp1P halves)
    uint32_t* swf = smu + 14336;    // 2 x 2048 (weffP chunks, dbl buf)
    int bm = blockIdx.y*128, bnb = blockIdx.x, bn = bnb*128;
    int b  = bm >> 10;
    int tid = threadIdx.x, wid = tid >> 5, lane = tid & 31;
    int g = lane >> 2, tig = lane & 3;
    int wm = (wid & 3)*32, wn = (wid >> 2)*64;
    uint32_t swp_u = smem_u32(swp), swf_u = smem_u32(swf);

    float ACC[2][8][4];
    #pragma unroll
    for (int i = 0; i < 2; i++)
        #pragma unroll
        for (int j = 0; j < 8; j++)
            #pragma unroll
            for (int q = 0; q < 4; q++) ACC[i][j][q] = 0.f;

    auto issue_chunk = [&](int t) {
        const uint32_t* src = g_weffP + ((size_t)((t >> 3)*2 + bnb)*8 + (t & 7))*2048 + tid*8;
        uint32_t dst = swf_u + ((uint32_t)(t & 1)*2048 + tid*8)*4;
        CP_ASYNC16(dst,      src);
        CP_ASYNC16(dst + 16, src + 4);
    };
    auto issue_swp = [&](int k) {
        const uint32_t* src = g_wp1P + (size_t)k*4096 + tid*16;
        uint32_t dst = swp_u + (uint32_t)tid*16*4;
        #pragma unroll
        for (int q = 0; q < 4; q++) CP_ASYNC16(dst + q*16, src + q*4);
    };

    issue_swp(0);
    issue_chunk(0);
    CP_COMMIT();

    int t = 0;
    const int TMAX = KF*8;
    for (int k = 0; k < KF; k++) {
        __syncthreads();     // sxc readers (gemm1 of k-1) done
        // xc A-chunk: pack f32 -> bf16x2 fragments (8 words/thread)
        {
            const float* Axc = g_xc + ((size_t)k*RTOT + bm)*32;
            #pragma unroll
            for (int q = 0; q < 8; q++) {
                int widx = tid + q*256;
                int tile = widx >> 7, lanep = (widx >> 2) & 31, aw = widx & 3;
                int mt = tile >> 1, kstep = tile & 1;
                int gp = lanep >> 2, tigp = lanep & 3;
                int row = mt*16 + (aw & 1)*8 + gp;
                int col = kstep*16 + (aw >> 1)*8 + tigp*2;
                float2 v = *(const float2*)(Axc + (size_t)row*32 + col);
                sxc[widx] = pack_bf16(v.x, v.y);
            }
        }
        CP_WAIT0();
        __syncthreads();     // swp(k), chunk t, sxc all visible
        #pragma unroll
        for (int h = 0; h < 2; h++) {
            // A fragments of xc (both ksteps, both m-tiles)
            uint32_t af[2][2][4];
            #pragma unroll
            for (int ks2 = 0; ks2 < 2; ks2++)
                #pragma unroll
                for (int i = 0; i < 2; i++) {
                    int tile = ((wid & 3)*2 + i)*2 + ks2;
                    *(uint4*)af[ks2][i] = *(const uint4*)&sxc[tile*128 + lane*4];
                }
            const float* ck = g_ckb + (size_t)(k*BB + b)*DD + h*128;
            __syncthreads();   // saA readers (prev gmma2) done
            // GEMM1 per j + fused gelu+scatter into saA
            #pragma unroll
            for (int j = 0; j < 8; j++) {
                float a1[2][4];
                #pragma unroll
                for (int i = 0; i < 2; i++)
                    #pragma unroll
                    for (int q = 0; q < 4; q++) a1[i][q] = 0.f;
                int nt = (wid >> 2)*8 + j;
                #pragma unroll
                for (int ks2 = 0; ks2 < 2; ks2++) {
                    uint32_t bfr[2];
                    bfr[0] = swp[h*2048 + (nt*2 + ks2)*64 + lane*2];
                    bfr[1] = swp[h*2048 + (nt*2 + ks2)*64 + lane*2 + 1];
                    mma_bf16(a1[0], af[ks2][0], bfr);
                    mma_bf16(a1[1], af[ks2][1], bfr);
                }
                int kcol = wn + j*8 + tig*2;      // 0..127 within half
                int cc = kcol >> 5, kk = kcol & 31;
                int kstep = kk >> 4, kk15 = kk & 15;
                int awc = (kk15 >= 8) ? 2 : 0;
                int tigd = (kk15 & 7) >> 1;
                float b0 = ck[kcol], b1 = ck[kcol + 1];
                #pragma unroll
                for (int i = 0; i < 2; i++) {
                    int mt = (wid & 3)*2 + i;
                    int base = cc*2048 + ((mt*2 + kstep)*32 + g*4 + tigd)*4;
                    saA[base + awc]     = pack_bf16(gelu_f(a1[i][0] + b0), gelu_f(a1[i][1] + b1));
                    saA[base + awc + 1] = pack_bf16(gelu_f(a1[i][2] + b0), gelu_f(a1[i][3] + b1));
                }
            }
            __syncthreads();   // saA visible
            #pragma unroll
            for (int cc = 0; cc < 4; cc++) {
                if (cc > 0 || h > 0) {
                    CP_WAIT0();
                    __syncthreads();   // chunk t visible; prior gmma done
                }
                bool iss = false;
                if (t + 1 < TMAX) { issue_chunk(t + 1); iss = true; }
                if ((t & 7) == 6 && k + 1 < KF) { issue_swp(k + 1); iss = true; }
                if (iss) CP_COMMIT();
                const uint32_t* Ac = saA + cc*2048;
                const uint32_t* Bc = swf + (t & 1)*2048;
                #pragma unroll
                for (int ks2 = 0; ks2 < 2; ks2++) {
                    uint32_t a2f[2][4];
                    #pragma unroll
                    for (int i = 0; i < 2; i++)
                        *(uint4*)a2f[i] = *(const uint4*)&Ac[(((wid & 3)*2 + i)*2 + ks2)*128 + lane*4];
                    #pragma unroll
                    for (int j = 0; j < 8; j++) {
                        int nt = (wid >> 2)*8 + j;
                        uint32_t bfr[2];
                        bfr[0] = Bc[(nt*2 + ks2)*64 + lane*2];
                        bfr[1] = Bc[(nt*2 + ks2)*64 + lane*2 + 1];
                        mma_bf16(ACC[0][j], a2f[0], bfr);
                        mma_bf16(ACC[1][j], a2f[1], bfr);
                    }
                }
                t++;
            }
        }
    }

    // epilogue
    #pragma unroll
    for (int i = 0; i < 2; i++) {
        int r0 = bm + wm + i*16 + g;
        #pragma unroll
        for (int j = 0; j < 8; j++) {
            int col = bn + wn + j*8 + tig*2;
            float b0 = g_bconst[col], b1 = g_bconst[col+1];
            float2 lo = make_float2(gelu_f(ACC[i][j][0] + b0), gelu_f(ACC[i][j][1] + b1));
            float2 hi = make_float2(gelu_f(ACC[i][j][2] + b0), gelu_f(ACC[i][j][3] + b1));
            *(float2*)(g_hf1 + (size_t)r0*256 + col)     = lo;
            *(float2*)(g_hf1 + (size_t)(r0+8)*256 + col) = hi;
        }
    }
}

// ---------------- weight transpose [K,N] -> [N,K] --------------------------
__global__ void k_tr(const float* __restrict__ W, float* __restrict__ WT, int K, int N)
{
    __shared__ float tile[32][33];
    int z = blockIdx.z;
    W  += (size_t)z*K*N;
    WT += (size_t)z*K*N;
    int k0 = blockIdx.y*32, n0 = blockIdx.x*32;
    int tx = threadIdx.x, ty = threadIdx.y;
    for (int i = ty; i < 32; i += 8) tile[i][tx] = W[(size_t)(k0+i)*N + n0+tx];
    __syncthreads();
    for (int i = ty; i < 32; i += 8) WT[(size_t)(n0+i)*K + k0+tx] = tile[tx][i];
}

// ---------------- k_uv partials: wp1 fold, split over e ---------------------
__global__ void k_uv1(const float* __restrict__ W, const float* __restrict__ W1)
{
    int bx = blockIdx.x;
    int k = bx >> 2, eq = bx & 3;
    int o = threadIdx.x;
    __shared__ float Ws[CC*DD];
    for (int i = o; i < CC*DD; i += 256) Ws[i] = W[i];
    __syncthreads();
    float acc[32];
    #pragma unroll
    for (int c = 0; c < 32; c++) acc[c] = 0.f;
    const float* w1 = W1 + (size_t)k*512*DD;
    for (int e = eq*64; e < eq*64 + 64; e++) {
        float u = w1[(size_t)e*DD + o];
        float v = w1[(size_t)(256+e)*DD + o];
        #pragma unroll
        for (int c = 0; c < 16; c++) {
            acc[c]      += Ws[c*DD + e]*u;
            acc[16 + c] += Ws[c*DD + e]*v;
        }
    }
    float* dst = g_uvp + ((size_t)(k*4 + eq)*DD + o)*32;
    #pragma unroll
    for (int c = 0; c < 32; c++) dst[c] = acc[c];
}
__global__ void k_uv2()
{
    int k = blockIdx.x, o = threadIdx.x;
    float* dst = g_wp1T + ((size_t)k*DD + o)*32;
    #pragma unroll
    for (int c = 0; c < 32; c++) {
        float s = 0.f;
        #pragma unroll
        for (int eq = 0; eq < 4; eq++)
            s += g_uvp[((size_t)(k*4 + eq)*DD + o)*32 + c];
        dst[c] = s;
    }
}

// ---------------- te DFT + te_att ------------------------------------------
__global__ void k_tedft(const float* __restrict__ in_proj_b)
{
    int b = blockIdx.x, e = threadIdx.x;
    float teb[PP];
    #pragma unroll
    for (int p = 0; p < PP; p++)
        teb[p] = g_time_emb[(b*PP + p)*DD + e] + in_proj_b[e];
    float ta = 0.f;
    #pragma unroll
    for (int p = 0; p < PP; p++) ta += g_att[b*PP + p]*teb[p];
    g_teatt[b*DD + e] = ta;
    for (int k = 0; k < KF; k++) {
        float re = 0.f, im = 0.f;
        #pragma unroll
        for (int p = 0; p < PP; p++) {
            re += teb[p]*g_tw[k*PP + p];
            im -= teb[p]*g_tw[KF*PP + k*PP + p];
        }
        g_tere[(k*BB + b)*DD + e] = re;
        g_teim[(k*BB + b)*DD + e] = im;
    }
}

// ---------------- c_kb[o] = b1_k[o] + Σ_e tere*W1_k[e][o] + teim*W1_k[256+e][o]
__global__ void k_ckb(const float* __restrict__ W1, const float* __restrict__ b1)
{
    int k = blockIdx.x, b = blockIdx.y, o = threadIdx.x;
    __shared__ float sre[DD], sim[DD];
    sre[o] = g_tere[(k*BB + b)*DD + o];
    sim[o] = g_teim[(k*BB + b)*DD + o];
    __syncthreads();
    float acc = b1[(size_t)k*DD + o];
    const float* w1 = W1 + (size_t)k*512*DD;
    for (int e = 0; e < 256; e++)
        acc += sre[e]*w1[(size_t)e*DD + o] + sim[e]*w1[(size_t)(256+e)*DD + o];
    g_ckb[(k*BB + b)*DD + o] = acc;
}

// ---------------- folded bias: bconst = comb_b1 + Σ b2·Wc1 (two-stage) -----
__global__ void k_bc1(const float* __restrict__ sfe_b2,
                      const float* __restrict__ comb_w1)
{
    int k = blockIdx.x, j = threadIdx.x;
    float s = 0.f;
    for (int i = k*256; i < k*256 + 256; i++)
        s += sfe_b2[i]*comb_w1[(size_t)i*256 + j];
    g_bcp[k*DD + j] = s;
}
__global__ void k_bc2(const float* __restrict__ comb_b1)
{
    int j = threadIdx.x;
    float s = comb_b1[j];
    #pragma unroll
    for (int k = 0; k < KF; k++) s += g_bcp[k*DD + j];
    g_bconst[j] = s;
}

// ---------------- tiny init ------------------------------------------------
__global__ void k_init(const float* __restrict__ pe_w1, const float* __restrict__ pe_b1,
                       const float* __restrict__ pe_w2, const float* __restrict__ pe_b2,
                       const float* __restrict__ pool_param)
{
    int t = threadIdx.x;
    for (int idx = t; idx < KF*PP; idx += blockDim.x) {
        int k = idx / PP, p = idx % PP;
        double ang = 2.0*M_PI*(double)(k*p)/24.0;
        g_tw[idx]        = (float)cos(ang);
        g_tw[KF*PP+idx]  = (float)sin(ang);
    }
    if (t < 2*PP) {
        int kk = t / PP, p = t % PP;
        double period = (kk == 0) ? 24.0 : 72.0;
        double ph = 2.0*M_PI*(double)p/period;
        float s = (float)sin(ph), c = (float)cos(ph);
        float hid[64];
        #pragma unroll
        for (int o = 0; o < 64; o++) {
            float v = s*pe_w1[kk*128 + o] + c*pe_w1[kk*128 + 64 + o] + pe_b1[kk*64 + o];
            hid[o] = gelu_f(v);
        }
        for (int q = 0; q < 64; q++) {
            float acc = pe_b2[kk*64 + q];
            #pragma unroll
            for (int o = 0; o < 64; o++) acc += hid[o]*pe_w2[kk*4096 + o*64 + q];
            g_periodic[p*128 + kk*64 + q] = acc;
        }
    }
    if (t == 0) {
        float mx = -1e30f;
        for (int p = 0; p < PP; p++) mx = fmaxf(mx, pool_param[p]);
        float se = 0.f, e[PP];
        for (int p = 0; p < PP; p++) { e[p] = expf(pool_param[p]-mx); se += e[p]; }
        for (int p = 0; p < PP; p++) g_base_att[p] = e[p]/se;
    }
}

// ---------------- spatial mean -> noise; assemble time_emb ----------------
__global__ void k_noise(const float* __restrict__ x, const float* __restrict__ noise_w,
                        const float* __restrict__ noise_b)
{
    int bp = blockIdx.x;
    int t  = threadIdx.x;
    __shared__ float partial[256];
    __shared__ float mean[CC];
    const float* xb = x + (size_t)bp*NN*CC;
    float acc = 0.f;
    for (int i = t; i < NN*CC; i += 256) acc += xb[i];
    partial[t] = acc;
    __syncthreads();
    if (t < CC) {
        float s = 0.f;
        for (int j = t; j < 256; j += CC) s += partial[j];
        mean[t] = s*(1.f/(float)NN);
    }
    __syncthreads();
    if (t < 128) {
        float nz = noise_b[t];
        #pragma unroll
        for (int c = 0; c < CC; c++) nz += mean[c]*noise_w[c*128 + t];
        g_time_emb[bp*DD + 128 + t] = nz;
        g_time_emb[bp*DD + t]       = g_periodic[(bp % PP)*128 + t];
    }
}

__global__ void k_timevec(float* __restrict__ out)
{
    int b = blockIdx.x, e = threadIdx.x;
    float s = 0.f;
    for (int p = 0; p < PP; p++) s += g_time_emb[(b*PP + p)*DD + e];
    out[(size_t)BB*NN*DD + b*DD + e] = s*(1.f/24.f);
}

// ---------------- x DFT + attention-weighted x -----------------------------
__global__ void __launch_bounds__(256) k_xdft(const float* __restrict__ x)
{
    __shared__ float twc[KF*PP], tws[KF*PP], atts[PP];
    int tid = threadIdx.x;
    int r = blockIdx.x*16 + (tid >> 4);
    int c = tid & 15;
    int b = r >> 10, n = r & 1023;
    for (int i = tid; i < KF*PP; i += 256) { twc[i] = g_tw[i]; tws[i] = g_tw[KF*PP + i]; }
    if (tid < PP) atts[tid] = g_att[b*PP + tid];
    __syncthreads();
    float re[KF], im[KF], xa = 0.f;
    #pragma unroll
    for (int k = 0; k < KF; k++) { re[k] = 0.f; im[k] = 0.f; }
    #pragma unroll
    for (int p = 0; p < PP; p++) {
        float xv = x[((size_t)(b*PP + p)*NN + n)*CC + c];
        xa += atts[p]*xv;
        #pragma unroll
        for (int k = 0; k < KF; k++) {
            re[k] += twc[k*PP + p]*xv;
            im[k] -= tws[k*PP + p]*xv;
        }
    }
    g_xatt[(size_t)r*CC + c] = xa;
    #pragma unroll
    for (int k = 0; k < KF; k++) {
        g_xc[((size_t)k*RTOT + r)*32 + c]      = re[k];
        g_xc[((size_t)k*RTOT + r)*32 + 16 + c] = im[k];
    }
}

// ---------------- zpart = xatt @ W + te_att --------------------------------
__global__ void k_zpart(const float* __restrict__ w)
{
    int blk = blockIdx.x;
    int r0 = blk*64;
    int b = r0 >> 10;
    int t = threadIdx.x;
    __shared__ float Ws[CC*DD];
    __shared__ float xs[64*CC];
    __shared__ float tb[DD];
    for (int i = t; i < CC*DD; i += 256) Ws[i] = w[i];
    tb[t] = g_teatt[b*DD + t];
    for (int i = t; i < 64*CC; i += 256) xs[i] = g_xatt[(size_t)r0*CC + i];
    __syncthreads();
    float* zp = g_zpart + (size_t)r0*DD;
    for (int nn = 0; nn < 64; nn++) {
        float acc = tb[t];
        #pragma unroll
        for (int c = 0; c < CC; c++) acc += xs[nn*CC + c]*Ws[c*DD + t];
        zp[(size_t)nn*DD + t] = acc;
    }
}

// ---------------- gating: lagged diffs over raw x -------------------------
__device__ __forceinline__ float xr_val(const float* __restrict__ xb, int p, int i)
{
    float xp = xb[(size_t)p*16384 + i];
    float base;
    if (p <= 1) base = xb[i];
    else base = (xb[(size_t)(p-2)*16384 + i] + xb[(size_t)(p-1)*16384 + i] + xp)*(1.f/3.f);
    return xp - base;
}

__global__ void k_gd(const float* __restrict__ x)
{
    int bp = blockIdx.x;
    int b = bp / PP, p = bp % PP;
    int t = threadIdx.x;
    const float* xb = x + (size_t)b*PP*16384;
    float s0=0.f, s1=0.f, s2=0.f, s3=0.f;
    for (int i = t; i < 16384; i += 256) {
        float xr_p = xr_val(xb, p, i);
        if (p >= 1) s0 += fabsf(xr_p - xr_val(xb, p-1, i));
        if (p >= 2) s1 += fabsf(xr_p - xr_val(xb, p-2, i));
        if (p >= 4) s2 += fabsf(xr_p - xr_val(xb, p-4, i));
        if (p >= 6) s3 += fabsf(xr_p - xr_val(xb, p-6, i));
    }
    __shared__ float red[4][256];
    red[0][t]=s0; red[1][t]=s1; red[2][t]=s2; red[3][t]=s3;
    __syncthreads();
    if (t < 4) {
        float ss = 0.f;
        for (int j = 0; j < 256; j++) ss += red[t][j];
        g_dd[(b*4 + t)*PP + p] = ss*(1.f/16384.f);
    }
}

__global__ void k_att()
{
    __shared__ float sp[BB][4][PP];
    int t = threadIdx.x;
    if (t < 32) {
        int b = t >> 2, l = t & 3;
        float dv[PP], srt[PP];
        for (int p = 0; p < PP; p++) dv[p] = g_dd[(b*4 + l)*PP + p];
        for (int p = 0; p < PP; p++) srt[p] = dv[p];
        isort(srt, PP);
        float med = srt[11];
        for (int p = 0; p < PP; p++) srt[p] = fabsf(dv[p] - med);
        isort(srt, PP);
        float mad = srt[11];
        float denom = mad*1.4826f + 1e-6f;
        for (int p = 0; p < PP; p++) {
            float zz = (dv[p] - med)/denom;
            sp[b][l][p] = softplus_f(zz);
        }
    }
    __syncthreads();
    if (t < BB) {
        int b = t;
        float g[PP];
        for (int p = 0; p < PP; p++)
            g[p] = 0.25f*(sp[b][0][p] + sp[b][1][p] + sp[b][2][p] + sp[b][3][p]);
        float c = g[0];
        for (int p = 1; p < PP; p++) { c = 0.6f*c + 0.4f*g[p]; g[p] = c; }
        float gm = 0.f;
        for (int p = 0; p < PP; p++) gm += g[p];
        gm *= (1.f/24.f);
        float logit[PP], mx = -1e30f;
        for (int p = 0; p < PP; p++) {
            float gg = 1.f/(1.f + expf(-1.5f*(g[p] - gm)));
            logit[p] = g_base_att[p]*(1.f + gg);
            mx = fmaxf(mx, logit[p]);
        }
        float se = 0.f;
        for (int p = 0; p < PP; p++) { logit[p] = expf(logit[p] - mx); se += logit[p]; }
        for (int p = 0; p < PP; p++) g_att[b*PP + p] = logit[p]/se;
    }
}

// ---------------- launch ---------------------------------------------------
extern "C" void kernel_launch(void* const* d_in, const int* in_sizes, int n_in,
                              void* d_out, int out_size)
{
    const float* x         = (const float*)d_in[0];
    const float* in_proj_w = (const float*)d_in[1];
    const float* in_proj_b = (const float*)d_in[2];
    const float* pe_w1     = (const float*)d_in[3];
    const float* pe_b1     = (const float*)d_in[4];
    const float* pe_w2     = (const float*)d_in[5];
    const float* pe_b2     = (const float*)d_in[6];
    const float* noise_w   = (const float*)d_in[7];
    const float* noise_b   = (const float*)d_in[8];
    const float* sfe_w1    = (const float*)d_in[9];
    const float* sfe_b1    = (const float*)d_in[10];
    const float* sfe_w2    = (const float*)d_in[11];
    const float* sfe_b2    = (const float*)d_in[12];
    const float* comb_w1   = (const float*)d_in[13];
    const float* comb_b1   = (const float*)d_in[14];
    const float* comb_w2   = (const float*)d_in[15];
    const float* comb_b2   = (const float*)d_in[16];
    const float* pool_param= (const float*)d_in[17];
    float* out = (float*)d_out;

    float *p_hf1, *p_wc1T, *p_weffT, *p_wc2T, *p_zero;
    cudaGetSymbolAddress((void**)&p_hf1,   g_hf1);
    cudaGetSymbolAddress((void**)&p_wc1T,  g_wc1T);
    cudaGetSymbolAddress((void**)&p_weffT, g_weffT);
    cudaGetSymbolAddress((void**)&p_wc2T,  g_wc2T);
    cudaGetSymbolAddress((void**)&p_zero,  g_zero);

    const int SMEM  = 16384*4;     // 64 KB for k_mma
    const int SMEMF = 18432*4;     // 72 KB for k_ff
    cudaFuncSetAttribute(k_mma<0,0>, cudaFuncAttributeMaxDynamicSharedMemorySize, SMEM);
    cudaFuncSetAttribute(k_mma<0,1>, cudaFuncAttributeMaxDynamicSharedMemorySize, SMEM);
    cudaFuncSetAttribute(k_ff,       cudaFuncAttributeMaxDynamicSharedMemorySize, SMEMF);

    // scalars / gating / embeddings
    k_init<<<1, 256>>>(pe_w1, pe_b1, pe_w2, pe_b2, pool_param);
    k_gd<<<BB*PP, 256>>>(x);
    k_att<<<1, 32>>>();
    k_noise<<<BB*PP, 256>>>(x, noise_w, noise_b);
    k_tedft<<<BB, 256>>>(in_proj_b);
    k_timevec<<<BB, 256>>>(out);

    // x-side folds
    k_xdft<<<RTOT/16, 256>>>(x);
    k_zpart<<<RTOT/64, 256>>>(in_proj_w);

    // weight prep
    dim3 trb(32, 8);
    k_uv1<<<KF*4, 256>>>(in_proj_w, sfe_w1);
    k_uv2<<<KF, 256>>>();
    k_ckb<<<dim3(KF, BB), 256>>>(sfe_w1, sfe_b1);
    k_tr<<<dim3(256/32, 256/32, KF), trb>>>(comb_w1, p_wc1T, 256, 256);
    k_tr<<<dim3(256/32, 256/32, 1),  trb>>>(comb_w2, p_wc2T, 256, 256);
    k_mma<0,0><<<dim3(2, 2, KF), 256, SMEM>>>(p_wc1T, sfe_w2, p_zero, p_weffT,
        256, 256, 65536L, 65536L, 0L, 65536L, 0);
    k_permW<<<KF*16, 256>>>();
    k_permP<<<KF*2, 256>>>();
    k_bc1<<<KF, 256>>>(sfe_b2, comb_w1);
    k_bc2<<<1, 256>>>(comb_b1);

    // fused sfe1 + sfe2·comb1: hf1 (bf16 tensor cores)
    k_ff<<<dim3(2, 64), 256, SMEMF>>>();
    // out = zpart + 0.3*(hf1 @ Wc2 + b2)
    k_mma<0,1><<<dim3(2, 64), 256, SMEM>>>(p_hf1, p_wc2T, comb_b2, out,
        256, 256, 0L, 0L, 0L, 0L, 0);
}

// round 17
// speedup vs baseline: 1.3113x; 1.0068x over previous
#include <cuda_runtime.h>
#include <cstdint>
#include <math.h>

#define BB 8
#define PP 24
#define CC 16
#define DD 256
#define NN 1024
#define KF 13
#define RTOT (BB*NN)      // 8192

// ---------------- scratch (device globals; no allocations) ----------------
__device__ __align__(128) float g_xc[(size_t)KF*RTOT*32];   // per-k [re(16)|im(16)]
__device__ __align__(128) float g_hf1[RTOT*DD];
__device__ __align__(128) float g_zpart[RTOT*DD];
__device__ __align__(128) float g_time_emb[BB*PP*DD];
__device__ __align__(128) float g_periodic[PP*128];
__device__ float g_base_att[PP];
__device__ float g_att[BB*PP];
__device__ float g_dd[BB*4*PP];
__device__ float g_tw[2*KF*PP];
__device__ float g_zero[DD];
__device__ float g_bconst[DD];
__device__ float g_bcp[KF*DD];
__device__ __align__(128) float g_tere[KF*BB*DD];
__device__ __align__(128) float g_teim[KF*BB*DD];
__device__ __align__(128) float g_teatt[BB*DD];
__device__ __align__(128) float g_ckb[KF*BB*DD];
// derived weights
__device__ __align__(128) float g_uvp[KF*4*DD*32];     // k_uv partials
__device__ __align__(128) float g_wc1T[KF*DD*DD];
__device__ __align__(128) float g_weffT[KF*DD*DD];
__device__ __align__(128) float g_wc2T[DD*DD];
// bf16 fragment-permuted copies for k_ff (packed bf16x2 words)
__device__ __align__(128) uint32_t g_weffP[(size_t)KF*2*8*2048];
__device__ __align__(128) uint32_t g_wp1P[KF*2*2048];

__device__ __forceinline__ float gelu_f(float v) {
    return 0.5f*v*(1.f + erff(v*0.70710678118654752f));
}
__device__ __forceinline__ float softplus_f(float v) {
    return fmaxf(v, 0.f) + log1pf(expf(-fabsf(v)));
}
__device__ void isort(float* a, int n) {
    for (int i = 1; i < n; i++) {
        float v = a[i]; int j = i-1;
        while (j >= 0 && a[j] > v) { a[j+1] = a[j]; j--; }
        a[j+1] = v;
    }
}
__device__ __forceinline__ float tf32r(float x) {
    uint32_t r;
    asm("cvt.rna.tf32.f32 %0, %1;" : "=r"(r) : "f"(x));
    return __uint_as_float(r);
}
__device__ __forceinline__ uint32_t pack_bf16(float lo, float hi) {
    uint32_t r;
    asm("cvt.rn.bf16x2.f32 %0, %1, %2;" : "=r"(r) : "f"(hi), "f"(lo));
    return r;
}
__device__ __forceinline__ uint32_t smem_u32(const void* p) {
    uint32_t a;
    asm("{ .reg .u64 t; cvta.to.shared.u64 t, %1; cvt.u32.u64 %0, t; }" : "=r"(a) : "l"(p));
    return a;
}
#define CP_ASYNC16(smaddr, gptr) \
    asm volatile("cp.async.ca.shared.global [%0], [%1], 16;" :: "r"(smaddr), "l"(gptr))
#define CP_COMMIT() asm volatile("cp.async.commit_group;" ::: "memory")
#define CP_WAIT0()  asm volatile("cp.async.wait_group 0;" ::: "memory")

// ---------------- warp mma --------------------------------------------------
__device__ __forceinline__ void mma_tf32(float* d, const float4& a, const float2& b) {
    asm volatile("mma.sync.aligned.m16n8k8.row.col.f32.tf32.tf32.f32 "
        "{%0,%1,%2,%3}, {%4,%5,%6,%7}, {%8,%9}, {%0,%1,%2,%3};"
        : "+f"(d[0]), "+f"(d[1]), "+f"(d[2]), "+f"(d[3])
        : "r"(__float_as_uint(a.x)), "r"(__float_as_uint(a.y)),
          "r"(__float_as_uint(a.z)), "r"(__float_as_uint(a.w)),
          "r"(__float_as_uint(b.x)), "r"(__float_as_uint(b.y)));
}
__device__ __forceinline__ void mma_bf16(float* d, const uint32_t* a, const uint32_t* b) {
    asm volatile("mma.sync.aligned.m16n8k16.row.col.f32.bf16.bf16.f32 "
        "{%0,%1,%2,%3}, {%4,%5,%6,%7}, {%8,%9}, {%0,%1,%2,%3};"
        : "+f"(d[0]), "+f"(d[1]), "+f"(d[2]), "+f"(d[3])
        : "r"(a[0]), "r"(a[1]), "r"(a[2]), "r"(a[3]), "r"(b[0]), "r"(b[1]));
}

// tf32 GEMM building blocks (CTA tile 128x128, 8 warps, K-chunk 32) -- k_mma
__device__ __forceinline__ void gload(const float* A, const float* Wt, int bm, int bn,
                                      int K, int koff, int tid, float4* ra, float4* rb)
{
    #pragma unroll
    for (int q = 0; q < 4; q++) {
        int f = tid + q*256;
        int row = f >> 3, seg = f & 7;
        ra[q] = *(const float4*)(A  + (size_t)(bm + row)*K + koff + seg*4);
        rb[q] = *(const float4*)(Wt + (size_t)(bn + row)*K + koff + seg*4);
    }
}
__device__ __forceinline__ void gscatter(const float4* ra, const float4* rb,
                                         float* sa, float* sb, int tid)
{
    #pragma unroll
    for (int q = 0; q < 4; q++) {
        int f = tid + q*256;
        int row = f >> 3, seg = f & 7;
        int ks = seg >> 1, posK = seg & 1;
        int mt = row >> 4, posM = (row >> 3) & 1, gga = row & 7;
        int abase = ((mt*4 + ks)*32 + gga*4)*4 + posK*2 + posM;
        float av[4] = {ra[q].x, ra[q].y, ra[q].z, ra[q].w};
        #pragma unroll
        for (int e = 0; e < 4; e++) sa[abase + e*4] = tf32r(av[e]);
        int nt = row >> 3, ggb = row & 7;
        int bbase = ((nt*4 + ks)*32 + ggb*4)*2 + posK;
        float bv[4] = {rb[q].x, rb[q].y, rb[q].z, rb[q].w};
        #pragma unroll
        for (int e = 0; e < 4; e++) sb[bbase + e*2] = tf32r(bv[e]);
    }
}
__device__ __forceinline__ void gmma(const float* sa, const float* sb,
                                     int wid, int lane, float acc[2][8][4])
{
    #pragma unroll
    for (int ks = 0; ks < 4; ks++) {
        float4 af[2];
        #pragma unroll
        for (int i = 0; i < 2; i++) {
            int mt = (wid & 3)*2 + i;
            af[i] = *(const float4*)&sa[((mt*4 + ks)*32 + lane)*4];
        }
        float2 bf[8];
        #pragma unroll
        for (int j = 0; j < 8; j++) {
            int nt = (wid >> 2)*8 + j;
            bf[j] = *(const float2*)&sb[((nt*4 + ks)*32 + lane)*2];
        }
        #pragma unroll
        for (int i = 0; i < 2; i++)
            #pragma unroll
            for (int j = 0; j < 8; j++)
                mma_tf32(acc[i][j], af[i], bf[j]);
    }
}

// ---------------- generic tf32 GEMM: C = act(A @ Wt^T + bias) --------------
template<int ACT, int FIN>
__global__ void __launch_bounds__(256) k_mma(
    const float* __restrict__ A, const float* __restrict__ Wt,
    const float* __restrict__ bias, float* __restrict__ C,
    int K, int ldc, long sA, long sW, long sB, long sC, int bstride)
{
    extern __shared__ float smem[];
    float* sa0 = smem;         float* sa1 = smem + 4096;
    float* sb0 = smem + 8192;  float* sb1 = smem + 12288;
    int z = blockIdx.z;
    int bm = blockIdx.y*128, bn = blockIdx.x*128;
    A    += (size_t)z*sA;
    Wt   += (size_t)z*sW;
    bias += (size_t)z*sB + (size_t)(bm >> 10)*bstride;
    C    += (size_t)z*sC;
    int tid = threadIdx.x, wid = tid >> 5, lane = tid & 31;
    int g = lane >> 2, tig = lane & 3;
    int wm = (wid & 3)*32, wn = (wid >> 2)*64;

    float acc[2][8][4];
    #pragma unroll
    for (int i = 0; i < 2; i++)
        #pragma unroll
        for (int j = 0; j < 8; j++)
            #pragma unroll
            for (int q = 0; q < 4; q++) acc[i][j][q] = 0.f;

    int nch = K >> 5;
    float4 ra[4], rb[4];
    gload(A, Wt, bm, bn, K, 0, tid, ra, rb);
    gscatter(ra, rb, sa0, sb0, tid);
    __syncthreads();
    for (int c = 0; c < nch; c++) {
        int buf = c & 1;
        if (c + 1 < nch) gload(A, Wt, bm, bn, K, (c+1)*32, tid, ra, rb);
        gmma(buf ? sa1 : sa0, buf ? sb1 : sb0, wid, lane, acc);
        if (c + 1 < nch) gscatter(ra, rb, buf ? sa0 : sa1, buf ? sb0 : sb1, tid);
        __syncthreads();
    }

    #pragma unroll
    for (int i = 0; i < 2; i++) {
        int r0 = bm + wm + i*16 + g;
        #pragma unroll
        for (int j = 0; j < 8; j++) {
            int col = bn + wn + j*8 + tig*2;
            float b0 = bias[col], b1 = bias[col+1];
            float v0 = acc[i][j][0] + b0, v1 = acc[i][j][1] + b1;
            float v2 = acc[i][j][2] + b0, v3 = acc[i][j][3] + b1;
            if (ACT) { v0 = gelu_f(v0); v1 = gelu_f(v1); v2 = gelu_f(v2); v3 = gelu_f(v3); }
            if (FIN) {
                v0 = g_zpart[(size_t)r0*ldc + col]       + 0.3f*v0;
                v1 = g_zpart[(size_t)r0*ldc + col + 1]   + 0.3f*v1;
                v2 = g_zpart[(size_t)(r0+8)*ldc + col]   + 0.3f*v2;
                v3 = g_zpart[(size_t)(r0+8)*ldc + col+1] + 0.3f*v3;
            }
            *(float2*)(C + (size_t)r0*ldc + col)     = make_float2(v0, v1);
            *(float2*)(C + (size_t)(r0+8)*ldc + col) = make_float2(v2, v3);
        }
    }
}

// ---------------- permute weffT chunks into bf16 B-fragment layout ---------
__global__ void k_permW()
{
    int bx = blockIdx.x;            // KF*16
    int k = bx >> 4, rem = bx & 15, bnb = rem >> 3, c8 = rem & 7;
    int tid = threadIdx.x;
    const float* src = g_weffT + (size_t)k*65536 + (size_t)bnb*128*256 + c8*32;
    uint32_t* dst = g_weffP + ((size_t)(k*2 + bnb)*8 + c8)*2048;
    #pragma unroll
    for (int q = 0; q < 8; q++) {
        int widx = tid + q*256;
        int tile = widx >> 6, lanep = (widx >> 1) & 31, w = widx & 1;
        int nt = tile >> 1, kstep = tile & 1;
        int gp = lanep >> 2, tigp = lanep & 3;
        int n = nt*8 + gp;
        int kk = kstep*16 + w*8 + tigp*2;
        float2 v = *(const float2*)(src + (size_t)n*256 + kk);
        dst[widx] = pack_bf16(v.x, v.y);
    }
}

// ---------------- permute wp1 (from uv partials) into bf16 B layout --------
__global__ void k_permP()
{
    int bx = blockIdx.x;            // KF*2
    int k = bx >> 1, h = bx & 1;
    int tid = threadIdx.x;
    uint32_t* dst = g_wp1P + (size_t)(k*2 + h)*2048;
    #pragma unroll
    for (int q = 0; q < 8; q++) {
        int widx = tid + q*256;
        int tile = widx >> 6, lanep = (widx >> 1) & 31, w = widx & 1;
        int nt = tile >> 1, kstep = tile & 1;
        int gp = lanep >> 2, tigp = lanep & 3;
        int o = h*128 + nt*8 + gp;
        int c = kstep*16 + w*8 + tigp*2;
        float lo = 0.f, hi = 0.f;
        #pragma unroll
        for (int eq = 0; eq < 4; eq++) {
            const float* u = g_uvp + ((size_t)(k*4 + eq)*DD + o)*32;
            lo += u[c]; hi += u[c+1];
        }
        dst[widx] = pack_bf16(lo, hi);
    }
}

// ---------------- fully fused bf16 m16n8k16 (M=128):
// hf1 = gelu(Σ_k gelu(xc_k@wp1T_k^T + ckb)@weffT_k + bconst)
__global__ void __launch_bounds__(256) k_ff()
{
    extern __shared__ uint32_t smu[];
    uint32_t* saA = smu;            // 4 chunks x 2048
    uint32_t* sxc = smu + 8192;     // 2048
    uint32_t* swp = smu + 10240;    // 2 x 2048
    uint32_t* swf = smu + 14336;    // 2 x 2048
    int bm = blockIdx.y*128, bnb = blockIdx.x, bn = bnb*128;
    int b  = bm >> 10;
    int tid = threadIdx.x, wid = tid >> 5, lane = tid & 31;
    int g = lane >> 2, tig = lane & 3;
    int wm = (wid & 3)*32, wn = (wid >> 2)*64;
    uint32_t swp_u = smem_u32(swp), swf_u = smem_u32(swf);

    float ACC[2][8][4];
    #pragma unroll
    for (int i = 0; i < 2; i++)
        #pragma unroll
        for (int j = 0; j < 8; j++)
            #pragma unroll
            for (int q = 0; q < 4; q++) ACC[i][j][q] = 0.f;

    auto issue_chunk = [&](int t) {
        const uint32_t* src = g_weffP + ((size_t)((t >> 3)*2 + bnb)*8 + (t & 7))*2048 + tid*8;
        uint32_t dst = swf_u + ((uint32_t)(t & 1)*2048 + tid*8)*4;
        CP_ASYNC16(dst,      src);
        CP_ASYNC16(dst + 16, src + 4);
    };
    auto issue_swp = [&](int k) {
        const uint32_t* src = g_wp1P + (size_t)k*4096 + tid*16;
        uint32_t dst = swp_u + (uint32_t)tid*16*4;
        #pragma unroll
        for (int q = 0; q < 4; q++) CP_ASYNC16(dst + q*16, src + q*4);
    };

    issue_swp(0);
    issue_chunk(0);
    CP_COMMIT();

    int t = 0;
    const int TMAX = KF*8;
    for (int k = 0; k < KF; k++) {
        __syncthreads();
        {
            const float* Axc = g_xc + ((size_t)k*RTOT + bm)*32;
            #pragma unroll
            for (int q = 0; q < 8; q++) {
                int widx = tid + q*256;
                int tile = widx >> 7, lanep = (widx >> 2) & 31, aw = widx & 3;
                int mt = tile >> 1, kstep = tile & 1;
                int gp = lanep >> 2, tigp = lanep & 3;
                int row = mt*16 + (aw & 1)*8 + gp;
                int col = kstep*16 + (aw >> 1)*8 + tigp*2;
                float2 v = *(const float2*)(Axc + (size_t)row*32 + col);
                sxc[widx] = pack_bf16(v.x, v.y);
            }
        }
        CP_WAIT0();
        __syncthreads();
        #pragma unroll
        for (int h = 0; h < 2; h++) {
            uint32_t af[2][2][4];
            #pragma unroll
            for (int ks2 = 0; ks2 < 2; ks2++)
                #pragma unroll
                for (int i = 0; i < 2; i++) {
                    int tile = ((wid & 3)*2 + i)*2 + ks2;
                    *(uint4*)af[ks2][i] = *(const uint4*)&sxc[tile*128 + lane*4];
                }
            const float* ck = g_ckb + (size_t)(k*BB + b)*DD + h*128;
            __syncthreads();
            #pragma unroll
            for (int j = 0; j < 8; j++) {
                float a1[2][4];
                #pragma unroll
                for (int i = 0; i < 2; i++)
                    #pragma unroll
                    for (int q = 0; q < 4; q++) a1[i][q] = 0.f;
                int nt = (wid >> 2)*8 + j;
                #pragma unroll
                for (int ks2 = 0; ks2 < 2; ks2++) {
                    uint32_t bfr[2];
                    bfr[0] = swp[h*2048 + (nt*2 + ks2)*64 + lane*2];
                    bfr[1] = swp[h*2048 + (nt*2 + ks2)*64 + lane*2 + 1];
                    mma_bf16(a1[0], af[ks2][0], bfr);
                    mma_bf16(a1[1], af[ks2][1], bfr);
                }
                int kcol = wn + j*8 + tig*2;
                int cc = kcol >> 5, kk = kcol & 31;
                int kstep = kk >> 4, kk15 = kk & 15;
                int awc = (kk15 >= 8) ? 2 : 0;
                int tigd = (kk15 & 7) >> 1;
                float b0 = ck[kcol], b1 = ck[kcol + 1];
                #pragma unroll
                for (int i = 0; i < 2; i++) {
                    int mt = (wid & 3)*2 + i;
                    int base = cc*2048 + ((mt*2 + kstep)*32 + g*4 + tigd)*4;
                    saA[base + awc]     = pack_bf16(gelu_f(a1[i][0] + b0), gelu_f(a1[i][1] + b1));
                    saA[base + awc + 1] = pack_bf16(gelu_f(a1[i][2] + b0), gelu_f(a1[i][3] + b1));
                }
            }
            __syncthreads();
            #pragma unroll
            for (int cc = 0; cc < 4; cc++) {
                if (cc > 0 || h > 0) {
                    CP_WAIT0();
                    __syncthreads();
                }
                bool iss = false;
                if (t + 1 < TMAX) { issue_chunk(t + 1); iss = true; }
                if ((t & 7) == 6 && k + 1 < KF) { issue_swp(k + 1); iss = true; }
                if (iss) CP_COMMIT();
                const uint32_t* Ac = saA + cc*2048;
                const uint32_t* Bc = swf + (t & 1)*2048;
                #pragma unroll
                for (int ks2 = 0; ks2 < 2; ks2++) {
                    uint32_t a2f[2][4];
                    #pragma unroll
                    for (int i = 0; i < 2; i++)
                        *(uint4*)a2f[i] = *(const uint4*)&Ac[(((wid & 3)*2 + i)*2 + ks2)*128 + lane*4];
                    #pragma unroll
                    for (int j = 0; j < 8; j++) {
                        int nt = (wid >> 2)*8 + j;
                        uint32_t bfr[2];
                        bfr[0] = Bc[(nt*2 + ks2)*64 + lane*2];
                        bfr[1] = Bc[(nt*2 + ks2)*64 + lane*2 + 1];
                        mma_bf16(ACC[0][j], a2f[0], bfr);
                        mma_bf16(ACC[1][j], a2f[1], bfr);
                    }
                }
                t++;
            }
        }
    }

    #pragma unroll
    for (int i = 0; i < 2; i++) {
        int r0 = bm + wm + i*16 + g;
        #pragma unroll
        for (int j = 0; j < 8; j++) {
            int col = bn + wn + j*8 + tig*2;
            float b0 = g_bconst[col], b1 = g_bconst[col+1];
            float2 lo = make_float2(gelu_f(ACC[i][j][0] + b0), gelu_f(ACC[i][j][1] + b1));
            float2 hi = make_float2(gelu_f(ACC[i][j][2] + b0), gelu_f(ACC[i][j][3] + b1));
            *(float2*)(g_hf1 + (size_t)r0*256 + col)     = lo;
            *(float2*)(g_hf1 + (size_t)(r0+8)*256 + col) = hi;
        }
    }
}

// ---------------- weight transpose [K,N] -> [N,K] --------------------------
__global__ void k_tr(const float* __restrict__ W, float* __restrict__ WT, int K, int N)
{
    __shared__ float tile[32][33];
    int z = blockIdx.z;
    W  += (size_t)z*K*N;
    WT += (size_t)z*K*N;
    int k0 = blockIdx.y*32, n0 = blockIdx.x*32;
    int tx = threadIdx.x, ty = threadIdx.y;
    for (int i = ty; i < 32; i += 8) tile[i][tx] = W[(size_t)(k0+i)*N + n0+tx];
    __syncthreads();
    for (int i = ty; i < 32; i += 8) WT[(size_t)(n0+i)*K + k0+tx] = tile[tx][i];
}

// ---------------- k_uv partials: wp1 fold, split over e ---------------------
__global__ void k_uv1(const float* __restrict__ W, const float* __restrict__ W1)
{
    int bx = blockIdx.x;
    int k = bx >> 2, eq = bx & 3;
    int o = threadIdx.x;
    __shared__ float Ws[CC*DD];
    for (int i = o; i < CC*DD; i += 256) Ws[i] = W[i];
    __syncthreads();
    float acc[32];
    #pragma unroll
    for (int c = 0; c < 32; c++) acc[c] = 0.f;
    const float* w1 = W1 + (size_t)k*512*DD;
    for (int e = eq*64; e < eq*64 + 64; e++) {
        float u = w1[(size_t)e*DD + o];
        float v = w1[(size_t)(256+e)*DD + o];
        #pragma unroll
        for (int c = 0; c < 16; c++) {
            acc[c]      += Ws[c*DD + e]*u;
            acc[16 + c] += Ws[c*DD + e]*v;
        }
    }
    float* dst = g_uvp + ((size_t)(k*4 + eq)*DD + o)*32;
    #pragma unroll
    for (int c = 0; c < 32; c++) dst[c] = acc[c];
}

// ---------------- te DFT + te_att ------------------------------------------
__global__ void k_tedft(const float* __restrict__ in_proj_b)
{
    int b = blockIdx.x, e = threadIdx.x;
    float teb[PP];
    #pragma unroll
    for (int p = 0; p < PP; p++)
        teb[p] = g_time_emb[(b*PP + p)*DD + e] + in_proj_b[e];
    float ta = 0.f;
    #pragma unroll
    for (int p = 0; p < PP; p++) ta += g_att[b*PP + p]*teb[p];
    g_teatt[b*DD + e] = ta;
    for (int k = 0; k < KF; k++) {
        float re = 0.f, im = 0.f;
        #pragma unroll
        for (int p = 0; p < PP; p++) {
            re += teb[p]*g_tw[k*PP + p];
            im -= teb[p]*g_tw[KF*PP + k*PP + p];
        }
        g_tere[(k*BB + b)*DD + e] = re;
        g_teim[(k*BB + b)*DD + e] = im;
    }
}

// ---------------- ckb: one block per k, all 8 b inside (W1 read once) ------
__global__ void k_ckb(const float* __restrict__ W1, const float* __restrict__ b1)
{
    int k = blockIdx.x, o = threadIdx.x;
    __shared__ float sre[BB][DD], sim[BB][DD];
    for (int b = 0; b < BB; b++) {
        sre[b][o] = g_tere[(k*BB + b)*DD + o];
        sim[b][o] = g_teim[(k*BB + b)*DD + o];
    }
    __syncthreads();
    float acc[BB];
    float bb = b1[(size_t)k*DD + o];
    #pragma unroll
    for (int b = 0; b < BB; b++) acc[b] = bb;
    const float* w1 = W1 + (size_t)k*512*DD;
    for (int e = 0; e < 256; e++) {
        float u = w1[(size_t)e*DD + o];
        float v = w1[(size_t)(256+e)*DD + o];
        #pragma unroll
        for (int b = 0; b < BB; b++)
            acc[b] += sre[b][e]*u + sim[b][e]*v;
    }
    for (int b = 0; b < BB; b++)
        g_ckb[(k*BB + b)*DD + o] = acc[b];
}

// ---------------- folded bias: bconst = comb_b1 + Σ b2·Wc1 (two-stage) -----
__global__ void k_bc1(const float* __restrict__ sfe_b2,
                      const float* __restrict__ comb_w1)
{
    int k = blockIdx.x, j = threadIdx.x;
    float s = 0.f;
    for (int i = k*256; i < k*256 + 256; i++)
        s += sfe_b2[i]*comb_w1[(size_t)i*256 + j];
    g_bcp[k*DD + j] = s;
}
__global__ void k_bc2(const float* __restrict__ comb_b1)
{
    int j = threadIdx.x;
    float s = comb_b1[j];
    #pragma unroll
    for (int k = 0; k < KF; k++) s += g_bcp[k*DD + j];
    g_bconst[j] = s;
}

// ---------------- tiny init ------------------------------------------------
__global__ void k_init(const float* __restrict__ pe_w1, const float* __restrict__ pe_b1,
                       const float* __restrict__ pe_w2, const float* __restrict__ pe_b2,
                       const float* __restrict__ pool_param)
{
    int t = threadIdx.x;
    for (int idx = t; idx < KF*PP; idx += blockDim.x) {
        int k = idx / PP, p = idx % PP;
        double ang = 2.0*M_PI*(double)(k*p)/24.0;
        g_tw[idx]        = (float)cos(ang);
        g_tw[KF*PP+idx]  = (float)sin(ang);
    }
    if (t < 2*PP) {
        int kk = t / PP, p = t % PP;
        double period = (kk == 0) ? 24.0 : 72.0;
        double ph = 2.0*M_PI*(double)p/period;
        float s = (float)sin(ph), c = (float)cos(ph);
        float hid[64];
        #pragma unroll
        for (int o = 0; o < 64; o++) {
            float v = s*pe_w1[kk*128 + o] + c*pe_w1[kk*128 + 64 + o] + pe_b1[kk*64 + o];
            hid[o] = gelu_f(v);
        }
        for (int q = 0; q < 64; q++) {
            float acc = pe_b2[kk*64 + q];
            #pragma unroll
            for (int o = 0; o < 64; o++) acc += hid[o]*pe_w2[kk*4096 + o*64 + q];
            g_periodic[p*128 + kk*64 + q] = acc;
        }
    }
    if (t == 0) {
        float mx = -1e30f;
        for (int p = 0; p < PP; p++) mx = fmaxf(mx, pool_param[p]);
        float se = 0.f, e[PP];
        for (int p = 0; p < PP; p++) { e[p] = expf(pool_param[p]-mx); se += e[p]; }
        for (int p = 0; p < PP; p++) g_base_att[p] = e[p]/se;
    }
}

// ---------------- spatial mean -> noise; assemble time_emb ----------------
__global__ void k_noise(const float* __restrict__ x, const float* __restrict__ noise_w,
                        const float* __restrict__ noise_b)
{
    int bp = blockIdx.x;
    int t  = threadIdx.x;
    __shared__ float partial[256];
    __shared__ float mean[CC];
    const float* xb = x + (size_t)bp*NN*CC;
    float acc = 0.f;
    for (int i = t; i < NN*CC; i += 256) acc += xb[i];
    partial[t] = acc;
    __syncthreads();
    if (t < CC) {
        float s = 0.f;
        for (int j = t; j < 256; j += CC) s += partial[j];
        mean[t] = s*(1.f/(float)NN);
    }
    __syncthreads();
    if (t < 128) {
        float nz = noise_b[t];
        #pragma unroll
        for (int c = 0; c < CC; c++) nz += mean[c]*noise_w[c*128 + t];
        g_time_emb[bp*DD + 128 + t] = nz;
        g_time_emb[bp*DD + t]       = g_periodic[(bp % PP)*128 + t];
    }
}

__global__ void k_timevec(float* __restrict__ out)
{
    int b = blockIdx.x, e = threadIdx.x;
    float s = 0.f;
    for (int p = 0; p < PP; p++) s += g_time_emb[(b*PP + p)*DD + e];
    out[(size_t)BB*NN*DD + b*DD + e] = s*(1.f/24.f);
}

// ---------------- x DFT + attention pooling + zpart (fused) ----------------
// block: 16 rows; threads (row, c). After DFT, compute zpart = xatt@W + teatt.
__global__ void __launch_bounds__(256) k_xdft(const float* __restrict__ x,
                                              const float* __restrict__ w)
{
    __shared__ float twc[KF*PP], tws[KF*PP], atts[PP];
    __shared__ float sxa[16][17];
    __shared__ float Ws[CC*DD];
    int tid = threadIdx.x;
    int r = blockIdx.x*16 + (tid >> 4);
    int c = tid & 15;
    int b = r >> 10, n = r & 1023;
    for (int i = tid; i < KF*PP; i += 256) { twc[i] = g_tw[i]; tws[i] = g_tw[KF*PP + i]; }
    for (int i = tid; i < CC*DD; i += 256) Ws[i] = w[i];
    if (tid < PP) atts[tid] = g_att[b*PP + tid];
    __syncthreads();
    float re[KF], im[KF], xa = 0.f;
    #pragma unroll
    for (int k = 0; k < KF; k++) { re[k] = 0.f; im[k] = 0.f; }
    #pragma unroll
    for (int p = 0; p < PP; p++) {
        float xv = x[((size_t)(b*PP + p)*NN + n)*CC + c];
        xa += atts[p]*xv;
        #pragma unroll
        for (int k = 0; k < KF; k++) {
            re[k] += twc[k*PP + p]*xv;
            im[k] -= tws[k*PP + p]*xv;
        }
    }
    sxa[tid >> 4][c] = xa;
    #pragma unroll
    for (int k = 0; k < KF; k++) {
        g_xc[((size_t)k*RTOT + r)*32 + c]      = re[k];
        g_xc[((size_t)k*RTOT + r)*32 + 16 + c] = im[k];
    }
    __syncthreads();
    // zpart: thread -> (row rl = tid>>4, 16 e-values at eoff)
    int rl = tid >> 4, eoff = (tid & 15)*16;
    int rg = blockIdx.x*16 + rl;
    float acc[16];
    #pragma unroll
    for (int ee = 0; ee < 16; ee++) acc[ee] = g_teatt[(rg >> 10)*DD + eoff + ee];
    #pragma unroll
    for (int cc2 = 0; cc2 < CC; cc2++) {
        float xv = sxa[rl][cc2];
        #pragma unroll
        for (int ee = 0; ee < 16; ee++)
            acc[ee] += xv*Ws[cc2*DD + eoff + ee];
    }
    #pragma unroll
    for (int ee = 0; ee < 16; ee += 4)
        *(float4*)(g_zpart + (size_t)rg*DD + eoff + ee) =
            make_float4(acc[ee], acc[ee+1], acc[ee+2], acc[ee+3]);
}

// ---------------- gating: lagged diffs over raw x (register-cached rows) ---
__global__ void k_gd(const float* __restrict__ x)
{
    int bp = blockIdx.x;
    int b = bp / PP, p = bp % PP;
    int t = threadIdx.x;
    const float* xb = x + (size_t)b*PP*16384;
    float s0=0.f, s1=0.f, s2=0.f, s3=0.f;
    for (int i = t; i < 16384; i += 256) {
        float val[9];
        #pragma unroll
        for (int j = 0; j < 9; j++) {
            int row = p - j;
            val[j] = (row >= 0) ? xb[(size_t)row*16384 + i] : 0.f;
        }
        // xr(q) with q = p - j
        auto xr = [&](int j) -> float {
            int q = p - j;
            if (q <= 1) return val[j] - val[p];            // base = row 0 (valid: q<=1 => p<=j+1 <=8)
            return val[j] - (val[j] + val[j+1] + val[j+2])*(1.f/3.f);
        };
        float xr0 = xr(0);
        if (p >= 1) s0 += fabsf(xr0 - xr(1));
        if (p >= 2) s1 += fabsf(xr0 - xr(2));
        if (p >= 4) s2 += fabsf(xr0 - xr(4));
        if (p >= 6) s3 += fabsf(xr0 - xr(6));
    }
    __shared__ float red[4][256];
    red[0][t]=s0; red[1][t]=s1; red[2][t]=s2; red[3][t]=s3;
    __syncthreads();
    if (t < 4) {
        float ss = 0.f;
        for (int j = 0; j < 256; j++) ss += red[t][j];
        g_dd[(b*4 + t)*PP + p] = ss*(1.f/16384.f);
    }
}

__global__ void k_att()
{
    __shared__ float sp[BB][4][PP];
    int t = threadIdx.x;
    if (t < 32) {
        int b = t >> 2, l = t & 3;
        float dv[PP], srt[PP];
        for (int p = 0; p < PP; p++) dv[p] = g_dd[(b*4 + l)*PP + p];
        for (int p = 0; p < PP; p++) srt[p] = dv[p];
        isort(srt, PP);
        float med = srt[11];
        for (int p = 0; p < PP; p++) srt[p] = fabsf(dv[p] - med);
        isort(srt, PP);
        float mad = srt[11];
        float denom = mad*1.4826f + 1e-6f;
        for (int p = 0; p < PP; p++) {
            float zz = (dv[p] - med)/denom;
            sp[b][l][p] = softplus_f(zz);
        }
    }
    __syncthreads();
    if (t < BB) {
        int b = t;
        float g[PP];
        for (int p = 0; p < PP; p++)
            g[p] = 0.25f*(sp[b][0][p] + sp[b][1][p] + sp[b][2][p] + sp[b][3][p]);
        float c = g[0];
        for (int p = 1; p < PP; p++) { c = 0.6f*c + 0.4f*g[p]; g[p] = c; }
        float gm = 0.f;
        for (int p = 0; p < PP; p++) gm += g[p];
        gm *= (1.f/24.f);
        float logit[PP], mx = -1e30f;
        for (int p = 0; p < PP; p++) {
            float gg = 1.f/(1.f + expf(-1.5f*(g[p] - gm)));
            logit[p] = g_base_att[p]*(1.f + gg);
            mx = fmaxf(mx, logit[p]);
        }
        float se = 0.f;
        for (int p = 0; p < PP; p++) { logit[p] = expf(logit[p] - mx); se += logit[p]; }
        for (int p = 0; p < PP; p++) g_att[b*PP + p] = logit[p]/se;
    }
}

// ---------------- launch ---------------------------------------------------
extern "C" void kernel_launch(void* const* d_in, const int* in_sizes, int n_in,
                              void* d_out, int out_size)
{
    const float* x         = (const float*)d_in[0];
    const float* in_proj_w = (const float*)d_in[1];
    const float* in_proj_b = (const float*)d_in[2];
    const float* pe_w1     = (const float*)d_in[3];
    const float* pe_b1     = (const float*)d_in[4];
    const float* pe_w2     = (const float*)d_in[5];
    const float* pe_b2     = (const float*)d_in[6];
    const float* noise_w   = (const float*)d_in[7];
    const float* noise_b   = (const float*)d_in[8];
    const float* sfe_w1    = (const float*)d_in[9];
    const float* sfe_b1    = (const float*)d_in[10];
    const float* sfe_w2    = (const float*)d_in[11];
    const float* sfe_b2    = (const float*)d_in[12];
    const float* comb_w1   = (const float*)d_in[13];
    const float* comb_b1   = (const float*)d_in[14];
    const float* comb_w2   = (const float*)d_in[15];
    const float* comb_b2   = (const float*)d_in[16];
    const float* pool_param= (const float*)d_in[17];
    float* out = (float*)d_out;

    float *p_hf1, *p_wc1T, *p_weffT, *p_wc2T, *p_zero;
    cudaGetSymbolAddress((void**)&p_hf1,   g_hf1);
    cudaGetSymbolAddress((void**)&p_wc1T,  g_wc1T);
    cudaGetSymbolAddress((void**)&p_weffT, g_weffT);
    cudaGetSymbolAddress((void**)&p_wc2T,  g_wc2T);
    cudaGetSymbolAddress((void**)&p_zero,  g_zero);

    const int SMEM  = 16384*4;     // 64 KB for k_mma
    const int SMEMF = 18432*4;     // 72 KB for k_ff
    cudaFuncSetAttribute(k_mma<0,0>, cudaFuncAttributeMaxDynamicSharedMemorySize, SMEM);
    cudaFuncSetAttribute(k_mma<0,1>, cudaFuncAttributeMaxDynamicSharedMemorySize, SMEM);
    cudaFuncSetAttribute(k_ff,       cudaFuncAttributeMaxDynamicSharedMemorySize, SMEMF);

    // scalars / gating / embeddings
    k_init<<<1, 256>>>(pe_w1, pe_b1, pe_w2, pe_b2, pool_param);
    k_gd<<<BB*PP, 256>>>(x);
    k_att<<<1, 32>>>();
    k_noise<<<BB*PP, 256>>>(x, noise_w, noise_b);
    k_tedft<<<BB, 256>>>(in_proj_b);
    k_timevec<<<BB, 256>>>(out);

    // x-side folds (DFT + zpart fused)
    k_xdft<<<RTOT/16, 256>>>(x, in_proj_w);

    // weight prep
    dim3 trb(32, 8);
    k_uv1<<<KF*4, 256>>>(in_proj_w, sfe_w1);
    k_ckb<<<KF, 256>>>(sfe_w1, sfe_b1);
    k_tr<<<dim3(256/32, 256/32, KF), trb>>>(comb_w1, p_wc1T, 256, 256);
    k_tr<<<dim3(256/32, 256/32, 1),  trb>>>(comb_w2, p_wc2T, 256, 256);
    k_mma<0,0><<<dim3(2, 2, KF), 256, SMEM>>>(p_wc1T, sfe_w2, p_zero, p_weffT,
        256, 256, 65536L, 65536L, 0L, 65536L, 0);
    k_permW<<<KF*16, 256>>>();
    k_permP<<<KF*2, 256>>>();
    k_bc1<<<KF, 256>>>(sfe_b2, comb_w1);
    k_bc2<<<1, 256>>>(comb_b1);

    // fused sfe1 + sfe2·comb1: hf1 (bf16 tensor cores)
    k_ff<<<dim3(2, 64), 256, SMEMF>>>();
    // out = zpart + 0.3*(hf1 @ Wc2 + b2)
    k_mma<0,1><<<dim3(2, 64), 256, SMEM>>>(p_hf1, p_wc2T, comb_b2, out,
        256, 256, 0L, 0L, 0L, 0L, 0);
}